// round 4
// baseline (speedup 1.0000x reference)
#include <cuda_runtime.h>
#include <cuda_fp16.h>
#include <cstdint>

// Problem dims (fixed by reference setup_inputs)
#define CDIM 32
#define NDIM 32
#define RDIM 256
#define LDIM 256
#define DDIM 512

// fp16 scratch copies of inputs + precomputed contract row norms
__device__ __half g_con_h[CDIM * RDIM * DDIM];   // 8 MB
__device__ __half g_law_h[NDIM * LDIM * DDIM];   // 8 MB
__device__ float  g_w1[CDIM * RDIM];

// ---------------- smem layout (bytes) ----------------
#define PSTR      264                     // P row stride in halves (256 + 8 pad)
#define P_BYTES   (LDIM * PSTR * 2)       // 135168
#define ST1       72                      // staging row stride in halves (64 + 8 pad)
#define LAW1_OFF  (P_BYTES)                       // 2 x 64*72*2   = 18432
#define CON1_OFF  (LAW1_OFF + 2 * 64 * ST1 * 2)   // 2 x 256*72*2  = 73728
#define LAW2_OFF  (P_BYTES)                       // phase-2 reuse of staging area
#define CON2_OFF  (P_BYTES + 256 * ST1 * 2)
#define W12_OFF   (CON1_OFF + 2 * 256 * ST1 * 2)  // 227328
#define W2_OFF    (W12_OFF + 256 * 4)
#define RED_OFF   (W2_OFF + 256 * 4)
#define SMEM_TOTAL (RED_OFF + 32 * 4)             // 229504 <= 232448 (227KB)

#define LEAKY 0.1f
#define SMOOTH 4.0f
#define LLSE 6.0f
#define SCALE_INV_SQRTD 0.04419417382415922f   // 1/sqrt(512)

// ---------------- PTX helpers ----------------
__device__ __forceinline__ uint32_t s2u(const void* p) {
    return (uint32_t)__cvta_generic_to_shared(p);
}
__device__ __forceinline__ void cp16(uint32_t dst, const void* src) {
    asm volatile("cp.async.cg.shared.global [%0], [%1], 16;\n" :: "r"(dst), "l"(src));
}
__device__ __forceinline__ void cp_commit() {
    asm volatile("cp.async.commit_group;\n");
}
__device__ __forceinline__ void ldsm_x4(uint32_t& r0, uint32_t& r1, uint32_t& r2, uint32_t& r3, uint32_t a) {
    asm volatile("ldmatrix.sync.aligned.m8n8.x4.shared.b16 {%0,%1,%2,%3}, [%4];\n"
                 : "=r"(r0), "=r"(r1), "=r"(r2), "=r"(r3) : "r"(a));
}
__device__ __forceinline__ void ldsm_x4t(uint32_t& r0, uint32_t& r1, uint32_t& r2, uint32_t& r3, uint32_t a) {
    asm volatile("ldmatrix.sync.aligned.m8n8.x4.trans.shared.b16 {%0,%1,%2,%3}, [%4];\n"
                 : "=r"(r0), "=r"(r1), "=r"(r2), "=r"(r3) : "r"(a));
}
__device__ __forceinline__ void mma16816(float* c,
                                         uint32_t a0, uint32_t a1, uint32_t a2, uint32_t a3,
                                         uint32_t b0, uint32_t b1) {
    asm volatile("mma.sync.aligned.m16n8k16.row.col.f32.f16.f16.f32 "
                 "{%0,%1,%2,%3}, {%4,%5,%6,%7}, {%8,%9}, {%0,%1,%2,%3};\n"
                 : "+f"(c[0]), "+f"(c[1]), "+f"(c[2]), "+f"(c[3])
                 : "r"(a0), "r"(a1), "r"(a2), "r"(a3), "r"(b0), "r"(b1));
}

// ---------------- pre-pass kernels ----------------
// One block per (c,r) row: fp32 -> fp16 convert + row norm.
__global__ void ctl_prep_con(const float* __restrict__ con) {
    int row = blockIdx.x;           // 0..8191
    int t = threadIdx.x;            // 128
    const float4* src = reinterpret_cast<const float4*>(con + (size_t)row * DDIM);
    float4 v = src[t];
    __half2* dst = reinterpret_cast<__half2*>(g_con_h + (size_t)row * DDIM);
    dst[2 * t + 0] = __floats2half2_rn(v.x, v.y);
    dst[2 * t + 1] = __floats2half2_rn(v.z, v.w);
    float ss = v.x * v.x + v.y * v.y + v.z * v.z + v.w * v.w;
    #pragma unroll
    for (int o = 16; o; o >>= 1) ss += __shfl_xor_sync(0xffffffffu, ss, o);
    __shared__ float red[4];
    if ((t & 31) == 0) red[t >> 5] = ss;
    __syncthreads();
    if (t == 0) g_w1[row] = sqrtf(red[0] + red[1] + red[2] + red[3]);
}

__global__ void ctl_prep_law(const float* __restrict__ law) {
    int row = blockIdx.x;
    int t = threadIdx.x;
    const float4* src = reinterpret_cast<const float4*>(law + (size_t)row * DDIM);
    float4 v = src[t];
    __half2* dst = reinterpret_cast<__half2*>(g_law_h + (size_t)row * DDIM);
    dst[2 * t + 0] = __floats2half2_rn(v.x, v.y);
    dst[2 * t + 1] = __floats2half2_rn(v.z, v.w);
}

// ---------------- main fused kernel: one CTA per (n, c) ----------------
__global__ __launch_bounds__(256, 1)
void ctl_main(const int* __restrict__ lens, float* __restrict__ out) {
    extern __shared__ char smem[];
    const int c = blockIdx.x;
    const int n = blockIdx.y;
    const int tid = threadIdx.x;
    const int wid = tid >> 5;
    const int lane = tid & 31;
    const int g = lane >> 2;      // groupID (row within 8)
    const int t4 = lane & 3;

    __half* P = (__half*)smem;                                 // [256][264] fp16 attn
    __half* law1 = (__half*)(smem + LAW1_OFF);                 // [2][64][72]
    __half* con1 = (__half*)(smem + CON1_OFF);                 // [2][256][72]
    const __half* lawg = g_law_h + (size_t)n * LDIM * DDIM;
    const __half* cong = g_con_h + (size_t)c * RDIM * DDIM;
    const int len = lens[n];

    // ================= Phase 1: attn = softmax-ops(laws @ con^T) into P =================
    const int wl = wid >> 1;      // 0..3 -> 16 l-rows each
    const int wr = wid & 1;       // 0..1 -> 128 r-cols each

    for (int lc = 0; lc < 4; lc++) {
        const int l0 = lc * 64;

        auto issue = [&](int kt) {
            int buf = kt & 1;
            __half* lb = law1 + buf * (64 * ST1);
            __half* cb = con1 + buf * (256 * ST1);
            #pragma unroll
            for (int i = 0; i < 2; i++) {          // laws: 64 rows x 8 chunks
                int id = tid + 256 * i;
                int row = id >> 3, ch = id & 7;
                cp16(s2u(lb + row * ST1 + ch * 8),
                     lawg + (size_t)(l0 + row) * DDIM + kt * 64 + ch * 8);
            }
            #pragma unroll
            for (int i = 0; i < 8; i++) {          // contracts: 256 rows x 8 chunks
                int id = tid + 256 * i;
                int row = id >> 3, ch = id & 7;
                cp16(s2u(cb + row * ST1 + ch * 8),
                     cong + (size_t)row * DDIM + kt * 64 + ch * 8);
            }
            cp_commit();
        };

        float acc[64];
        #pragma unroll
        for (int i = 0; i < 64; i++) acc[i] = 0.f;

        issue(0);
        for (int kt = 0; kt < 8; kt++) {
            if (kt < 7) {
                issue(kt + 1);
                asm volatile("cp.async.wait_group 1;\n");
            } else {
                asm volatile("cp.async.wait_group 0;\n");
            }
            __syncthreads();
            int buf = kt & 1;
            const __half* lb = law1 + buf * (64 * ST1);
            const __half* cb = con1 + buf * (256 * ST1);
            #pragma unroll
            for (int ks = 0; ks < 4; ks++) {
                uint32_t a0, a1, a2, a3;
                {
                    int row = wl * 16 + (lane & 15);
                    int col = ks * 16 + (lane >> 4) * 8;
                    ldsm_x4(a0, a1, a2, a3, s2u(lb + row * ST1 + col));
                }
                #pragma unroll
                for (int np = 0; np < 8; np++) {
                    uint32_t b0, b1, b2, b3;
                    int n0 = wr * 128 + np * 16;
                    int row = n0 + (lane & 7) + ((lane >> 4) << 3);
                    int col = ks * 16 + ((lane >> 3) & 1) * 8;
                    ldsm_x4(b0, b1, b2, b3, s2u(cb + row * ST1 + col));
                    mma16816(acc + (np * 2 + 0) * 4, a0, a1, a2, a3, b0, b1);
                    mma16816(acc + (np * 2 + 1) * 4, a0, a1, a2, a3, b2, b3);
                }
            }
            __syncthreads();
        }

        // scale + leaky-relu, store S chunk into P (fp16)
        {
            int lrow0 = l0 + wl * 16 + g;
            #pragma unroll
            for (int nt = 0; nt < 16; nt++) {
                int rb = wr * 128 + nt * 8 + 2 * t4;
                float v0 = acc[nt * 4 + 0] * SCALE_INV_SQRTD;
                float v1 = acc[nt * 4 + 1] * SCALE_INV_SQRTD;
                float v2 = acc[nt * 4 + 2] * SCALE_INV_SQRTD;
                float v3 = acc[nt * 4 + 3] * SCALE_INV_SQRTD;
                v0 = (v0 >= 0.f) ? v0 : LEAKY * v0;
                v1 = (v1 >= 0.f) ? v1 : LEAKY * v1;
                v2 = (v2 >= 0.f) ? v2 : LEAKY * v2;
                v3 = (v3 >= 0.f) ? v3 : LEAKY * v3;
                *(__half2*)&P[(size_t)lrow0 * PSTR + rb]       = __floats2half2_rn(v0, v1);
                *(__half2*)&P[(size_t)(lrow0 + 8) * PSTR + rb] = __floats2half2_rn(v2, v3);
            }
        }
        __syncthreads();

        // row ops (per l-row over full R): l2norm -> softmax -> *SMOOTH -> mask
        for (int rr = 0; rr < 8; rr++) {
            int l = l0 + wid * 8 + rr;
            __half2* prow = (__half2*)&P[(size_t)l * PSTR];
            float v[8];
            float ss = 0.f;
            #pragma unroll
            for (int j = 0; j < 4; j++) {
                __half2 h = prow[lane + 32 * j];
                float x = __low2float(h), y = __high2float(h);
                v[2 * j] = x; v[2 * j + 1] = y;
                ss += x * x + y * y;
            }
            #pragma unroll
            for (int o = 16; o; o >>= 1) ss += __shfl_xor_sync(0xffffffffu, ss, o);
            float inv = 1.f / (sqrtf(ss) + 1e-8f);
            float es = 0.f;
            #pragma unroll
            for (int j = 0; j < 8; j++) {
                v[j] = __expf(v[j] * inv);
                es += v[j];
            }
            #pragma unroll
            for (int o = 16; o; o >>= 1) es += __shfl_xor_sync(0xffffffffu, es, o);
            float zf = (l < len) ? (SMOOTH / es) : 0.f;
            #pragma unroll
            for (int j = 0; j < 4; j++)
                prow[lane + 32 * j] = __floats2half2_rn(v[2 * j] * zf, v[2 * j + 1] * zf);
        }
        __syncthreads();
    }

    // ================= Phase 2: wlaw = P^T @ laws, fused cosine partials =================
    __half* law2 = (__half*)(smem + LAW2_OFF);   // [256][72]
    __half* con2 = (__half*)(smem + CON2_OFF);   // [256][72]
    float* w12s = (float*)(smem + W12_OFF);
    float* w2s  = (float*)(smem + W2_OFF);

    float w12a[4] = {0.f, 0.f, 0.f, 0.f};
    float w2a[4]  = {0.f, 0.f, 0.f, 0.f};
    const int rbase = wid * 32;

    for (int dt = 0; dt < 8; dt++) {
        #pragma unroll
        for (int i = 0; i < 8; i++) {
            int id = tid + 256 * i;
            int row = id >> 3, ch = id & 7;
            cp16(s2u(law2 + row * ST1 + ch * 8),
                 lawg + (size_t)row * DDIM + dt * 64 + ch * 8);
        }
        #pragma unroll
        for (int i = 0; i < 8; i++) {
            int id = tid + 256 * i;
            int row = id >> 3, ch = id & 7;
            cp16(s2u(con2 + row * ST1 + ch * 8),
                 cong + (size_t)row * DDIM + dt * 64 + ch * 8);
        }
        cp_commit();
        asm volatile("cp.async.wait_group 0;\n");
        __syncthreads();

        float acc[64];
        #pragma unroll
        for (int i = 0; i < 64; i++) acc[i] = 0.f;

        #pragma unroll 4
        for (int ks = 0; ks < 16; ks++) {
            int l0k = ks * 16;
            uint32_t a[2][4];
            #pragma unroll
            for (int mt = 0; mt < 2; mt++) {
                int r0 = rbase + mt * 16;
                int row = l0k + (lane & 7) + ((lane & 16) >> 1);
                int col = r0 + (lane & 8);
                ldsm_x4t(a[mt][0], a[mt][1], a[mt][2], a[mt][3],
                         s2u(&P[(size_t)row * PSTR + col]));
            }
            #pragma unroll
            for (int np = 0; np < 4; np++) {
                uint32_t b0, b1, b2, b3;
                int d0 = np * 16;
                int row = l0k + (lane & 7) + (lane & 8);
                int col = d0 + ((lane & 16) >> 1);
                ldsm_x4t(b0, b1, b2, b3, s2u(&law2[row * ST1 + col]));
                mma16816(acc + (0 * 8 + np * 2 + 0) * 4, a[0][0], a[0][1], a[0][2], a[0][3], b0, b1);
                mma16816(acc + (0 * 8 + np * 2 + 1) * 4, a[0][0], a[0][1], a[0][2], a[0][3], b2, b3);
                mma16816(acc + (1 * 8 + np * 2 + 0) * 4, a[1][0], a[1][1], a[1][2], a[1][3], b0, b1);
                mma16816(acc + (1 * 8 + np * 2 + 1) * 4, a[1][0], a[1][1], a[1][2], a[1][3], b2, b3);
            }
        }

        // cosine partials for this d-tile
        #pragma unroll
        for (int mt = 0; mt < 2; mt++) {
            #pragma unroll
            for (int s = 0; s < 2; s++) {
                int r = rbase + mt * 16 + g + 8 * s;
                float pw12 = 0.f, pw2 = 0.f;
                #pragma unroll
                for (int nt = 0; nt < 8; nt++) {
                    float o0 = acc[(mt * 8 + nt) * 4 + 2 * s + 0];
                    float o1 = acc[(mt * 8 + nt) * 4 + 2 * s + 1];
                    __half2 chh = *(const __half2*)&con2[r * ST1 + nt * 8 + 2 * t4];
                    pw12 += o0 * __low2float(chh) + o1 * __high2float(chh);
                    pw2  += o0 * o0 + o1 * o1;
                }
                pw12 += __shfl_xor_sync(0xffffffffu, pw12, 1);
                pw12 += __shfl_xor_sync(0xffffffffu, pw12, 2);
                pw2  += __shfl_xor_sync(0xffffffffu, pw2, 1);
                pw2  += __shfl_xor_sync(0xffffffffu, pw2, 2);
                w12a[mt * 2 + s] += pw12;
                w2a[mt * 2 + s]  += pw2;
            }
        }
        __syncthreads();   // before next tile overwrites law2/con2
    }

    if (t4 == 0) {
        #pragma unroll
        for (int mt = 0; mt < 2; mt++)
            #pragma unroll
            for (int s = 0; s < 2; s++) {
                int r = rbase + mt * 16 + g + 8 * s;
                w12s[r] = w12a[mt * 2 + s];
                w2s[r]  = w2a[mt * 2 + s];
            }
    }
    __syncthreads();

    // ================= sim + LogSumExp over regions =================
    {
        int r = tid;
        float w2 = sqrtf(w2s[r]);
        float denom = fmaxf(g_w1[c * RDIM + r] * w2, 1e-8f);
        float sim = w12s[r] / denom;
        float e = __expf(LLSE * sim);
        #pragma unroll
        for (int o = 16; o; o >>= 1) e += __shfl_xor_sync(0xffffffffu, e, o);
        float* red = (float*)(smem + RED_OFF);
        if (lane == 0) red[wid] = e;
        __syncthreads();
        if (tid == 0) {
            float s = 0.f;
            #pragma unroll
            for (int i = 0; i < 8; i++) s += red[i];
            out[c * NDIM + n] = logf(s) * (1.0f / LLSE);
        }
    }
}

// ---------------- launch ----------------
extern "C" void kernel_launch(void* const* d_in, const int* in_sizes, int n_in,
                              void* d_out, int out_size) {
    const float* contracts = (const float*)d_in[0];   // [32,256,512] fp32
    const float* laws      = (const float*)d_in[1];   // [32,256,512] fp32
    const int*   law_lens  = (const int*)d_in[2];     // [32] int32
    float* out = (float*)d_out;                        // [32,32] fp32

    cudaFuncSetAttribute(ctl_main, cudaFuncAttributeMaxDynamicSharedMemorySize, SMEM_TOTAL);

    ctl_prep_con<<<CDIM * RDIM, 128>>>(contracts);
    ctl_prep_law<<<NDIM * LDIM, 128>>>(laws);
    ctl_main<<<dim3(CDIM, NDIM), 256, SMEM_TOTAL>>>(law_lens, out);
}

// round 6
// speedup vs baseline: 1.0280x; 1.0280x over previous
#include <cuda_runtime.h>
#include <cuda_fp16.h>
#include <cstdint>

// Problem dims (fixed by reference setup_inputs)
#define CDIM 32
#define NDIM 32
#define RDIM 256
#define LDIM 256
#define DDIM 512

// fp16 scratch copies of inputs + precomputed contract row norms
__device__ __half g_con_h[CDIM * RDIM * DDIM];   // 8 MB
__device__ __half g_law_h[NDIM * LDIM * DDIM];   // 8 MB
__device__ float  g_w1[CDIM * RDIM];

// ---------------- smem layout (bytes) ----------------
#define PSTR      264                     // P row stride in halves (256 + 8 pad)
#define P_BYTES   (LDIM * PSTR * 2)       // 135168
#define ST1       72                      // staging row stride in halves (64 + 8 pad)
#define LAW1_OFF  (P_BYTES)                       // 2 x 64*72*2   = 18432
#define CON1_OFF  (LAW1_OFF + 2 * 64 * ST1 * 2)   // 2 x 256*72*2  = 73728
#define LAW2_OFF  (P_BYTES)                       // phase-2: 2 x 256*72*2 (reuse)
#define W12_OFF   (CON1_OFF + 2 * 256 * ST1 * 2)  // 227328
#define W2_OFF    (W12_OFF + 256 * 4)
#define RED_OFF   (W2_OFF + 256 * 4)
#define SMEM_TOTAL (RED_OFF + 8 * 4)              // 229408 <= 232448

#define LEAKY 0.1f
#define SMOOTH 4.0f
#define LLSE 6.0f
#define SCALE_INV_SQRTD 0.04419417382415922f   // 1/sqrt(512)

// ---------------- PTX helpers ----------------
__device__ __forceinline__ uint32_t s2u(const void* p) {
    return (uint32_t)__cvta_generic_to_shared(p);
}
__device__ __forceinline__ void cp16(uint32_t dst, const void* src) {
    asm volatile("cp.async.cg.shared.global [%0], [%1], 16;\n" :: "r"(dst), "l"(src));
}
__device__ __forceinline__ void cp_commit() {
    asm volatile("cp.async.commit_group;\n");
}
__device__ __forceinline__ void ldsm_x4(uint32_t& r0, uint32_t& r1, uint32_t& r2, uint32_t& r3, uint32_t a) {
    asm volatile("ldmatrix.sync.aligned.m8n8.x4.shared.b16 {%0,%1,%2,%3}, [%4];\n"
                 : "=r"(r0), "=r"(r1), "=r"(r2), "=r"(r3) : "r"(a));
}
__device__ __forceinline__ void ldsm_x4t(uint32_t& r0, uint32_t& r1, uint32_t& r2, uint32_t& r3, uint32_t a) {
    asm volatile("ldmatrix.sync.aligned.m8n8.x4.trans.shared.b16 {%0,%1,%2,%3}, [%4];\n"
                 : "=r"(r0), "=r"(r1), "=r"(r2), "=r"(r3) : "r"(a));
}
__device__ __forceinline__ void mma16816(float* c,
                                         uint32_t a0, uint32_t a1, uint32_t a2, uint32_t a3,
                                         uint32_t b0, uint32_t b1) {
    asm volatile("mma.sync.aligned.m16n8k16.row.col.f32.f16.f16.f32 "
                 "{%0,%1,%2,%3}, {%4,%5,%6,%7}, {%8,%9}, {%0,%1,%2,%3};\n"
                 : "+f"(c[0]), "+f"(c[1]), "+f"(c[2]), "+f"(c[3])
                 : "r"(a0), "r"(a1), "r"(a2), "r"(a3), "r"(b0), "r"(b1));
}

// ---------------- pre-pass kernels ----------------
__global__ void ctl_prep_con(const float* __restrict__ con) {
    int row = blockIdx.x;           // 0..8191
    int t = threadIdx.x;            // 128
    const float4* src = reinterpret_cast<const float4*>(con + (size_t)row * DDIM);
    float4 v = src[t];
    __half2* dst = reinterpret_cast<__half2*>(g_con_h + (size_t)row * DDIM);
    dst[2 * t + 0] = __floats2half2_rn(v.x, v.y);
    dst[2 * t + 1] = __floats2half2_rn(v.z, v.w);
    float ss = v.x * v.x + v.y * v.y + v.z * v.z + v.w * v.w;
    #pragma unroll
    for (int o = 16; o; o >>= 1) ss += __shfl_xor_sync(0xffffffffu, ss, o);
    __shared__ float red[4];
    if ((t & 31) == 0) red[t >> 5] = ss;
    __syncthreads();
    if (t == 0) g_w1[row] = sqrtf(red[0] + red[1] + red[2] + red[3]);
}

__global__ void ctl_prep_law(const float* __restrict__ law) {
    int row = blockIdx.x;
    int t = threadIdx.x;
    const float4* src = reinterpret_cast<const float4*>(law + (size_t)row * DDIM);
    float4 v = src[t];
    __half2* dst = reinterpret_cast<__half2*>(g_law_h + (size_t)row * DDIM);
    dst[2 * t + 0] = __floats2half2_rn(v.x, v.y);
    dst[2 * t + 1] = __floats2half2_rn(v.z, v.w);
}

// ---------------- main fused kernel: one CTA per (n, c), 512 threads ----------------
__global__ __launch_bounds__(512, 1)
void ctl_main(const int* __restrict__ lens, float* __restrict__ out) {
    extern __shared__ char smem[];
    const int c = blockIdx.x;
    const int n = blockIdx.y;
    const int tid = threadIdx.x;
    const int wid = tid >> 5;        // 0..15
    const int lane = tid & 31;
    const int g = lane >> 2;         // row within 8
    const int t4 = lane & 3;

    __half* P = (__half*)smem;                                 // [256][264] fp16 attn
    __half* law1 = (__half*)(smem + LAW1_OFF);                 // [2][64][72]
    __half* con1 = (__half*)(smem + CON1_OFF);                 // [2][256][72]
    const __half* lawg = g_law_h + (size_t)n * LDIM * DDIM;
    const __half* cong = g_con_h + (size_t)c * RDIM * DDIM;
    const int len = lens[n];

    // ================= Phase 1: attn = softmax-ops(laws @ con^T) into P =================
    const int wl = wid >> 2;      // 0..3 -> 16 l-rows each
    const int wr = wid & 3;       // 0..3 -> 64 r-cols each

    for (int lc = 0; lc < 4; lc++) {
        const int l0 = lc * 64;

        auto issue = [&](int kt) {
            int buf = kt & 1;
            __half* lb = law1 + buf * (64 * ST1);
            __half* cb = con1 + buf * (256 * ST1);
            {   // laws: 64 rows x 8 chunks = 512 -> 1 per thread
                int row = tid >> 3, ch = tid & 7;
                cp16(s2u(lb + row * ST1 + ch * 8),
                     lawg + (size_t)(l0 + row) * DDIM + kt * 64 + ch * 8);
            }
            #pragma unroll
            for (int i = 0; i < 4; i++) {          // contracts: 256 rows x 8 chunks
                int id = tid + 512 * i;
                int row = id >> 3, ch = id & 7;
                cp16(s2u(cb + row * ST1 + ch * 8),
                     cong + (size_t)row * DDIM + kt * 64 + ch * 8);
            }
            cp_commit();
        };

        float acc[32];
        #pragma unroll
        for (int i = 0; i < 32; i++) acc[i] = 0.f;

        issue(0);
        for (int kt = 0; kt < 8; kt++) {
            if (kt < 7) {
                issue(kt + 1);
                asm volatile("cp.async.wait_group 1;\n");
            } else {
                asm volatile("cp.async.wait_group 0;\n");
            }
            __syncthreads();
            int buf = kt & 1;
            const __half* lb = law1 + buf * (64 * ST1);
            const __half* cb = con1 + buf * (256 * ST1);
            #pragma unroll
            for (int ks = 0; ks < 4; ks++) {
                uint32_t a0, a1, a2, a3;
                {
                    int row = wl * 16 + (lane & 15);
                    int col = ks * 16 + (lane >> 4) * 8;
                    ldsm_x4(a0, a1, a2, a3, s2u(lb + row * ST1 + col));
                }
                #pragma unroll
                for (int np = 0; np < 4; np++) {
                    uint32_t b0, b1, b2, b3;
                    int n0 = wr * 64 + np * 16;
                    int row = n0 + (lane & 7) + ((lane >> 4) << 3);
                    int col = ks * 16 + ((lane >> 3) & 1) * 8;
                    ldsm_x4(b0, b1, b2, b3, s2u(cb + row * ST1 + col));
                    mma16816(acc + (np * 2 + 0) * 4, a0, a1, a2, a3, b0, b1);
                    mma16816(acc + (np * 2 + 1) * 4, a0, a1, a2, a3, b2, b3);
                }
            }
            __syncthreads();
        }

        // scale + leaky-relu, store S chunk into P (fp16)
        {
            int lrow0 = l0 + wl * 16 + g;
            #pragma unroll
            for (int nt = 0; nt < 8; nt++) {
                int rb = wr * 64 + nt * 8 + 2 * t4;
                float v0 = acc[nt * 4 + 0] * SCALE_INV_SQRTD;
                float v1 = acc[nt * 4 + 1] * SCALE_INV_SQRTD;
                float v2 = acc[nt * 4 + 2] * SCALE_INV_SQRTD;
                float v3 = acc[nt * 4 + 3] * SCALE_INV_SQRTD;
                v0 = (v0 >= 0.f) ? v0 : LEAKY * v0;
                v1 = (v1 >= 0.f) ? v1 : LEAKY * v1;
                v2 = (v2 >= 0.f) ? v2 : LEAKY * v2;
                v3 = (v3 >= 0.f) ? v3 : LEAKY * v3;
                *(__half2*)&P[(size_t)lrow0 * PSTR + rb]       = __floats2half2_rn(v0, v1);
                *(__half2*)&P[(size_t)(lrow0 + 8) * PSTR + rb] = __floats2half2_rn(v2, v3);
            }
        }
        __syncthreads();

        // row ops (per l-row over full R): l2norm -> softmax -> *SMOOTH -> mask
        for (int rr = 0; rr < 4; rr++) {
            int l = l0 + wid * 4 + rr;
            __half2* prow = (__half2*)&P[(size_t)l * PSTR];
            float v[8];
            float ss = 0.f;
            #pragma unroll
            for (int j = 0; j < 4; j++) {
                __half2 h = prow[lane + 32 * j];
                float x = __low2float(h), y = __high2float(h);
                v[2 * j] = x; v[2 * j + 1] = y;
                ss += x * x + y * y;
            }
            #pragma unroll
            for (int o = 16; o; o >>= 1) ss += __shfl_xor_sync(0xffffffffu, ss, o);
            float inv = 1.f / (sqrtf(ss) + 1e-8f);
            float es = 0.f;
            #pragma unroll
            for (int j = 0; j < 8; j++) {
                v[j] = __expf(v[j] * inv);
                es += v[j];
            }
            #pragma unroll
            for (int o = 16; o; o >>= 1) es += __shfl_xor_sync(0xffffffffu, es, o);
            float zf = (l < len) ? (SMOOTH / es) : 0.f;
            #pragma unroll
            for (int j = 0; j < 4; j++)
                prow[lane + 32 * j] = __floats2half2_rn(v[2 * j] * zf, v[2 * j + 1] * zf);
        }
        __syncthreads();
    }

    // ================= Phase 2: wlaw = P^T @ laws, fused cosine partials =================
    // 16 warps: rbase = (wid>>1)*32 (32 r-rows), dhalf = (wid&1)*32 (32 d-cols per 64-chunk)
    __half* law2 = (__half*)(smem + LAW2_OFF);   // [2][256][72]
    float* w12s = (float*)(smem + W12_OFF);
    float* w2s  = (float*)(smem + W2_OFF);

    float w12a[4] = {0.f, 0.f, 0.f, 0.f};
    float w2a[4]  = {0.f, 0.f, 0.f, 0.f};
    const int rbase = (wid >> 1) * 32;
    const int dhalf = (wid & 1) * 32;

    auto stage2 = [&](int dt) {
        __half* lb = law2 + (dt & 1) * (256 * ST1);
        #pragma unroll
        for (int i = 0; i < 4; i++) {
            int id = tid + 512 * i;
            int row = id >> 3, ch = id & 7;
            cp16(s2u(lb + row * ST1 + ch * 8),
                 lawg + (size_t)row * DDIM + dt * 64 + ch * 8);
        }
        cp_commit();
    };

    stage2(0);
    for (int dt = 0; dt < 8; dt++) {
        if (dt < 7) {
            stage2(dt + 1);
            asm volatile("cp.async.wait_group 1;\n");
        } else {
            asm volatile("cp.async.wait_group 0;\n");
        }
        __syncthreads();
        const __half* lb = law2 + (dt & 1) * (256 * ST1);

        float acc[32];
        #pragma unroll
        for (int i = 0; i < 32; i++) acc[i] = 0.f;

        #pragma unroll 4
        for (int ks = 0; ks < 16; ks++) {
            int l0k = ks * 16;
            uint32_t a[2][4];
            #pragma unroll
            for (int mt = 0; mt < 2; mt++) {
                int r0 = rbase + mt * 16;
                int row = l0k + (lane & 7) + ((lane & 16) >> 1);
                int col = r0 + (lane & 8);
                ldsm_x4t(a[mt][0], a[mt][1], a[mt][2], a[mt][3],
                         s2u(&P[(size_t)row * PSTR + col]));
            }
            #pragma unroll
            for (int np = 0; np < 2; np++) {
                uint32_t b0, b1, b2, b3;
                int d0 = dhalf + np * 16;
                int row = l0k + (lane & 7) + (lane & 8);
                int col = d0 + ((lane & 16) >> 1);
                ldsm_x4t(b0, b1, b2, b3, s2u(&lb[row * ST1 + col]));
                mma16816(acc + (0 * 4 + np * 2 + 0) * 4, a[0][0], a[0][1], a[0][2], a[0][3], b0, b1);
                mma16816(acc + (0 * 4 + np * 2 + 1) * 4, a[0][0], a[0][1], a[0][2], a[0][3], b2, b3);
                mma16816(acc + (1 * 4 + np * 2 + 0) * 4, a[1][0], a[1][1], a[1][2], a[1][3], b0, b1);
                mma16816(acc + (1 * 4 + np * 2 + 1) * 4, a[1][0], a[1][1], a[1][2], a[1][3], b2, b3);
            }
        }

        // cosine partials (con read straight from L2-resident global)
        #pragma unroll
        for (int mt = 0; mt < 2; mt++) {
            #pragma unroll
            for (int s = 0; s < 2; s++) {
                int r = rbase + mt * 16 + g + 8 * s;
                const __half2* crow = (const __half2*)(cong + (size_t)r * DDIM + dt * 64 + dhalf + 2 * t4);
                float pw12 = 0.f, pw2 = 0.f;
                #pragma unroll
                for (int j = 0; j < 4; j++) {
                    float o0 = acc[(mt * 4 + j) * 4 + 2 * s + 0];
                    float o1 = acc[(mt * 4 + j) * 4 + 2 * s + 1];
                    __half2 chh = crow[j * 4];      // 8 halves apart = 4 half2
                    pw12 += o0 * __low2float(chh) + o1 * __high2float(chh);
                    pw2  += o0 * o0 + o1 * o1;
                }
                w12a[mt * 2 + s] += pw12;
                w2a[mt * 2 + s]  += pw2;
            }
        }
        __syncthreads();   // before next dt's compute consumes freshly staged buffer
    }

    // reduce partials across t4 quad (r owned by 4 lanes with same g) and across d-halves
    #pragma unroll
    for (int i = 0; i < 4; i++) {
        w12a[i] += __shfl_xor_sync(0xffffffffu, w12a[i], 1);
        w12a[i] += __shfl_xor_sync(0xffffffffu, w12a[i], 2);
        w2a[i]  += __shfl_xor_sync(0xffffffffu, w2a[i], 1);
        w2a[i]  += __shfl_xor_sync(0xffffffffu, w2a[i], 2);
    }
    // the two d-half warps (wid even/odd, same rbase) both hold partials for the same r.
    // combine via smem: even warp writes, odd warp adds.
    if ((wid & 1) == 0 && t4 == 0) {
        #pragma unroll
        for (int mt = 0; mt < 2; mt++)
            #pragma unroll
            for (int s = 0; s < 2; s++) {
                int r = rbase + mt * 16 + g + 8 * s;
                w12s[r] = w12a[mt * 2 + s];
                w2s[r]  = w2a[mt * 2 + s];
            }
    }
    __syncthreads();
    if ((wid & 1) == 1 && t4 == 0) {
        #pragma unroll
        for (int mt = 0; mt < 2; mt++)
            #pragma unroll
            for (int s = 0; s < 2; s++) {
                int r = rbase + mt * 16 + g + 8 * s;
                w12s[r] += w12a[mt * 2 + s];
                w2s[r]  += w2a[mt * 2 + s];
            }
    }
    __syncthreads();

    // ================= sim + LogSumExp over regions =================
    if (tid < 256) {
        int r = tid;
        float w2 = sqrtf(w2s[r]);
        float denom = fmaxf(g_w1[c * RDIM + r] * w2, 1e-8f);
        float sim = w12s[r] / denom;
        float e = __expf(LLSE * sim);
        #pragma unroll
        for (int o = 16; o; o >>= 1) e += __shfl_xor_sync(0xffffffffu, e, o);
        float* red = (float*)(smem + RED_OFF);
        if (lane == 0) red[wid] = e;
    }
    __syncthreads();
    if (tid == 0) {
        float* red = (float*)(smem + RED_OFF);
        float s = 0.f;
        #pragma unroll
        for (int i = 0; i < 8; i++) s += red[i];
        out[c * NDIM + n] = logf(s) * (1.0f / LLSE);
    }
}

// ---------------- launch ----------------
extern "C" void kernel_launch(void* const* d_in, const int* in_sizes, int n_in,
                              void* d_out, int out_size) {
    const float* contracts = (const float*)d_in[0];   // [32,256,512] fp32
    const float* laws      = (const float*)d_in[1];   // [32,256,512] fp32
    const int*   law_lens  = (const int*)d_in[2];     // [32] int32
    float* out = (float*)d_out;                        // [32,32] fp32

    cudaFuncSetAttribute(ctl_main, cudaFuncAttributeMaxDynamicSharedMemorySize, SMEM_TOTAL);

    ctl_prep_con<<<CDIM * RDIM, 128>>>(contracts);
    ctl_prep_law<<<NDIM * LDIM, 128>>>(laws);
    ctl_main<<<dim3(CDIM, NDIM), 512, SMEM_TOTAL>>>(law_lens, out);
}

// round 7
// speedup vs baseline: 1.0844x; 1.0549x over previous
#include <cuda_runtime.h>
#include <cuda_fp16.h>
#include <cstdint>

// Problem dims (fixed by reference setup_inputs)
#define CDIM 32
#define NDIM 32
#define RDIM 256
#define LDIM 256
#define DDIM 512

// fp16 scratch copies of inputs + precomputed contract row norms
__device__ __half g_con_h[CDIM * RDIM * DDIM];   // 8 MB
__device__ __half g_law_h[NDIM * LDIM * DDIM];   // 8 MB
__device__ float  g_w1[CDIM * RDIM];

// ---------------- smem layout (bytes) ----------------
#define PSTR      264                     // P row stride in halves (256 + 8 pad)
#define P_BYTES   (LDIM * PSTR * 2)       // 135168
#define ST1       72                      // staging row stride in halves (64 + 8 pad)
#define LAW1_OFF  (P_BYTES)                       // 2 x 64*72*2   = 18432
#define CON1_OFF  (LAW1_OFF + 2 * 64 * ST1 * 2)   // 2 x 256*72*2  = 73728
#define LAW2_OFF  (P_BYTES)                       // phase-2: 2 x 256*72*2 (reuse)
#define W12_OFF   (CON1_OFF + 2 * 256 * ST1 * 2)  // 227328
#define W2_OFF    (W12_OFF + 256 * 4)
#define RED_OFF   (W2_OFF + 256 * 4)
#define SMEM_TOTAL (RED_OFF + 8 * 4)              // 229408 <= 232448

#define LEAKY 0.1f
#define SMOOTH 4.0f
#define LLSE 6.0f
#define SCALE_INV_SQRTD 0.04419417382415922f   // 1/sqrt(512)

// ---------------- PTX helpers ----------------
__device__ __forceinline__ uint32_t s2u(const void* p) {
    return (uint32_t)__cvta_generic_to_shared(p);
}
__device__ __forceinline__ void cp16(uint32_t dst, const void* src) {
    asm volatile("cp.async.cg.shared.global [%0], [%1], 16;\n" :: "r"(dst), "l"(src));
}
__device__ __forceinline__ void cp_commit() {
    asm volatile("cp.async.commit_group;\n");
}
__device__ __forceinline__ void ldsm_x4(uint32_t& r0, uint32_t& r1, uint32_t& r2, uint32_t& r3, uint32_t a) {
    asm volatile("ldmatrix.sync.aligned.m8n8.x4.shared.b16 {%0,%1,%2,%3}, [%4];\n"
                 : "=r"(r0), "=r"(r1), "=r"(r2), "=r"(r3) : "r"(a));
}
__device__ __forceinline__ void ldsm_x4t(uint32_t& r0, uint32_t& r1, uint32_t& r2, uint32_t& r3, uint32_t a) {
    asm volatile("ldmatrix.sync.aligned.m8n8.x4.trans.shared.b16 {%0,%1,%2,%3}, [%4];\n"
                 : "=r"(r0), "=r"(r1), "=r"(r2), "=r"(r3) : "r"(a));
}
__device__ __forceinline__ void mma16816(float* c,
                                         uint32_t a0, uint32_t a1, uint32_t a2, uint32_t a3,
                                         uint32_t b0, uint32_t b1) {
    asm volatile("mma.sync.aligned.m16n8k16.row.col.f32.f16.f16.f32 "
                 "{%0,%1,%2,%3}, {%4,%5,%6,%7}, {%8,%9}, {%0,%1,%2,%3};\n"
                 : "+f"(c[0]), "+f"(c[1]), "+f"(c[2]), "+f"(c[3])
                 : "r"(a0), "r"(a1), "r"(a2), "r"(a3), "r"(b0), "r"(b1));
}

// ---------------- pre-pass kernels ----------------
__global__ void ctl_prep_con(const float* __restrict__ con) {
    int row = blockIdx.x;           // 0..8191
    int t = threadIdx.x;            // 128
    const float4* src = reinterpret_cast<const float4*>(con + (size_t)row * DDIM);
    float4 v = src[t];
    __half2* dst = reinterpret_cast<__half2*>(g_con_h + (size_t)row * DDIM);
    dst[2 * t + 0] = __floats2half2_rn(v.x, v.y);
    dst[2 * t + 1] = __floats2half2_rn(v.z, v.w);
    float ss = v.x * v.x + v.y * v.y + v.z * v.z + v.w * v.w;
    #pragma unroll
    for (int o = 16; o; o >>= 1) ss += __shfl_xor_sync(0xffffffffu, ss, o);
    __shared__ float red[4];
    if ((t & 31) == 0) red[t >> 5] = ss;
    __syncthreads();
    if (t == 0) g_w1[row] = sqrtf(red[0] + red[1] + red[2] + red[3]);
}

__global__ void ctl_prep_law(const float* __restrict__ law) {
    int row = blockIdx.x;
    int t = threadIdx.x;
    const float4* src = reinterpret_cast<const float4*>(law + (size_t)row * DDIM);
    float4 v = src[t];
    __half2* dst = reinterpret_cast<__half2*>(g_law_h + (size_t)row * DDIM);
    dst[2 * t + 0] = __floats2half2_rn(v.x, v.y);
    dst[2 * t + 1] = __floats2half2_rn(v.z, v.w);
}

// ---------------- main fused kernel: one CTA per (n, c), 512 threads ----------------
__global__ __launch_bounds__(512, 1)
void ctl_main(const int* __restrict__ lens, float* __restrict__ out) {
    extern __shared__ char smem[];
    const int c = blockIdx.x;
    const int n = blockIdx.y;
    const int tid = threadIdx.x;
    const int wid = tid >> 5;        // 0..15
    const int lane = tid & 31;
    const int g = lane >> 2;         // row within 8
    const int t4 = lane & 3;

    __half* P = (__half*)smem;                                 // [256][264] fp16 attn
    __half* law1 = (__half*)(smem + LAW1_OFF);                 // [2][64][72]
    __half* con1 = (__half*)(smem + CON1_OFF);                 // [2][256][72]
    const __half* lawg = g_law_h + (size_t)n * LDIM * DDIM;
    const __half* cong = g_con_h + (size_t)c * RDIM * DDIM;
    const int len = lens[n];
    const int lcmax = (len + 63) >> 6;    // 2..4 phase-1 l-chunks actually needed
    const int ksmax = (len + 15) >> 4;    // 8..16 phase-2 k-chunks actually needed

    // ================= Phase 1: attn = softmax-ops(laws @ con^T) into P =================
    const int wl = wid >> 2;      // 0..3 -> 16 l-rows each
    const int wr = wid & 3;       // 0..3 -> 64 r-cols each

    for (int lc = 0; lc < lcmax; lc++) {
        const int l0 = lc * 64;

        auto issue = [&](int kt) {
            int buf = kt & 1;
            __half* lb = law1 + buf * (64 * ST1);
            __half* cb = con1 + buf * (256 * ST1);
            {   // laws: 64 rows x 8 chunks = 512 -> 1 per thread
                int row = tid >> 3, ch = tid & 7;
                cp16(s2u(lb + row * ST1 + ch * 8),
                     lawg + (size_t)(l0 + row) * DDIM + kt * 64 + ch * 8);
            }
            #pragma unroll
            for (int i = 0; i < 4; i++) {          // contracts: 256 rows x 8 chunks
                int id = tid + 512 * i;
                int row = id >> 3, ch = id & 7;
                cp16(s2u(cb + row * ST1 + ch * 8),
                     cong + (size_t)row * DDIM + kt * 64 + ch * 8);
            }
            cp_commit();
        };

        float acc[32];
        #pragma unroll
        for (int i = 0; i < 32; i++) acc[i] = 0.f;

        issue(0);
        for (int kt = 0; kt < 8; kt++) {
            if (kt < 7) {
                issue(kt + 1);
                asm volatile("cp.async.wait_group 1;\n");
            } else {
                asm volatile("cp.async.wait_group 0;\n");
            }
            __syncthreads();
            int buf = kt & 1;
            const __half* lb = law1 + buf * (64 * ST1);
            const __half* cb = con1 + buf * (256 * ST1);
            #pragma unroll
            for (int ks = 0; ks < 4; ks++) {
                uint32_t a0, a1, a2, a3;
                {
                    int row = wl * 16 + (lane & 15);
                    int col = ks * 16 + (lane >> 4) * 8;
                    ldsm_x4(a0, a1, a2, a3, s2u(lb + row * ST1 + col));
                }
                #pragma unroll
                for (int np = 0; np < 4; np++) {
                    uint32_t b0, b1, b2, b3;
                    int n0 = wr * 64 + np * 16;
                    int row = n0 + (lane & 7) + ((lane >> 4) << 3);
                    int col = ks * 16 + ((lane >> 3) & 1) * 8;
                    ldsm_x4(b0, b1, b2, b3, s2u(cb + row * ST1 + col));
                    mma16816(acc + (np * 2 + 0) * 4, a0, a1, a2, a3, b0, b1);
                    mma16816(acc + (np * 2 + 1) * 4, a0, a1, a2, a3, b2, b3);
                }
            }
            __syncthreads();
        }

        // scale + leaky-relu, store S chunk into P (fp16)
        {
            int lrow0 = l0 + wl * 16 + g;
            #pragma unroll
            for (int nt = 0; nt < 8; nt++) {
                int rb = wr * 64 + nt * 8 + 2 * t4;
                float v0 = acc[nt * 4 + 0] * SCALE_INV_SQRTD;
                float v1 = acc[nt * 4 + 1] * SCALE_INV_SQRTD;
                float v2 = acc[nt * 4 + 2] * SCALE_INV_SQRTD;
                float v3 = acc[nt * 4 + 3] * SCALE_INV_SQRTD;
                v0 = (v0 >= 0.f) ? v0 : LEAKY * v0;
                v1 = (v1 >= 0.f) ? v1 : LEAKY * v1;
                v2 = (v2 >= 0.f) ? v2 : LEAKY * v2;
                v3 = (v3 >= 0.f) ? v3 : LEAKY * v3;
                *(__half2*)&P[(size_t)lrow0 * PSTR + rb]       = __floats2half2_rn(v0, v1);
                *(__half2*)&P[(size_t)(lrow0 + 8) * PSTR + rb] = __floats2half2_rn(v2, v3);
            }
        }
        __syncthreads();

        // row ops (per l-row over full R): l2norm -> softmax -> *SMOOTH -> mask
        for (int rr = 0; rr < 4; rr++) {
            int l = l0 + wid * 4 + rr;
            __half2* prow = (__half2*)&P[(size_t)l * PSTR];
            float v[8];
            float ss = 0.f;
            #pragma unroll
            for (int j = 0; j < 4; j++) {
                __half2 h = prow[lane + 32 * j];
                float x = __low2float(h), y = __high2float(h);
                v[2 * j] = x; v[2 * j + 1] = y;
                ss += x * x + y * y;
            }
            #pragma unroll
            for (int o = 16; o; o >>= 1) ss += __shfl_xor_sync(0xffffffffu, ss, o);
            float inv = 1.f / (sqrtf(ss) + 1e-8f);
            float es = 0.f;
            #pragma unroll
            for (int j = 0; j < 8; j++) {
                v[j] = __expf(v[j] * inv);
                es += v[j];
            }
            #pragma unroll
            for (int o = 16; o; o >>= 1) es += __shfl_xor_sync(0xffffffffu, es, o);
            float zf = (l < len) ? (SMOOTH / es) : 0.f;
            #pragma unroll
            for (int j = 0; j < 4; j++)
                prow[lane + 32 * j] = __floats2half2_rn(v[2 * j] * zf, v[2 * j + 1] * zf);
        }
        __syncthreads();
    }

    // ================= Phase 2: wlaw = P^T @ laws, fused cosine partials =================
    // 16 warps: rbase = (wid>>1)*32 (32 r-rows), dhalf = (wid&1)*32 (32 d-cols per 64-chunk)
    // contraction over l runs only where attn can be nonzero: ks < ksmax (rest is exactly 0)
    __half* law2 = (__half*)(smem + LAW2_OFF);   // [2][256][72]
    float* w12s = (float*)(smem + W12_OFF);
    float* w2s  = (float*)(smem + W2_OFF);

    float w12a[4] = {0.f, 0.f, 0.f, 0.f};
    float w2a[4]  = {0.f, 0.f, 0.f, 0.f};
    const int rbase = (wid >> 1) * 32;
    const int dhalf = (wid & 1) * 32;

    auto stage2 = [&](int dt) {
        __half* lb = law2 + (dt & 1) * (256 * ST1);
        #pragma unroll
        for (int i = 0; i < 4; i++) {
            int id = tid + 512 * i;
            int row = id >> 3, ch = id & 7;
            cp16(s2u(lb + row * ST1 + ch * 8),
                 lawg + (size_t)row * DDIM + dt * 64 + ch * 8);
        }
        cp_commit();
    };

    stage2(0);
    for (int dt = 0; dt < 8; dt++) {
        if (dt < 7) {
            stage2(dt + 1);
            asm volatile("cp.async.wait_group 1;\n");
        } else {
            asm volatile("cp.async.wait_group 0;\n");
        }
        __syncthreads();
        const __half* lb = law2 + (dt & 1) * (256 * ST1);

        float acc[32];
        #pragma unroll
        for (int i = 0; i < 32; i++) acc[i] = 0.f;

        #pragma unroll 4
        for (int ks = 0; ks < ksmax; ks++) {
            int l0k = ks * 16;
            uint32_t a[2][4];
            #pragma unroll
            for (int mt = 0; mt < 2; mt++) {
                int r0 = rbase + mt * 16;
                int row = l0k + (lane & 7) + ((lane & 16) >> 1);
                int col = r0 + (lane & 8);
                ldsm_x4t(a[mt][0], a[mt][1], a[mt][2], a[mt][3],
                         s2u(&P[(size_t)row * PSTR + col]));
            }
            #pragma unroll
            for (int np = 0; np < 2; np++) {
                uint32_t b0, b1, b2, b3;
                int d0 = dhalf + np * 16;
                int row = l0k + (lane & 7) + (lane & 8);
                int col = d0 + ((lane & 16) >> 1);
                ldsm_x4t(b0, b1, b2, b3, s2u(&lb[row * ST1 + col]));
                mma16816(acc + (0 * 4 + np * 2 + 0) * 4, a[0][0], a[0][1], a[0][2], a[0][3], b0, b1);
                mma16816(acc + (0 * 4 + np * 2 + 1) * 4, a[0][0], a[0][1], a[0][2], a[0][3], b2, b3);
                mma16816(acc + (1 * 4 + np * 2 + 0) * 4, a[1][0], a[1][1], a[1][2], a[1][3], b0, b1);
                mma16816(acc + (1 * 4 + np * 2 + 1) * 4, a[1][0], a[1][1], a[1][2], a[1][3], b2, b3);
            }
        }

        // cosine partials (con read straight from L2-resident global)
        #pragma unroll
        for (int mt = 0; mt < 2; mt++) {
            #pragma unroll
            for (int s = 0; s < 2; s++) {
                int r = rbase + mt * 16 + g + 8 * s;
                const __half2* crow = (const __half2*)(cong + (size_t)r * DDIM + dt * 64 + dhalf + 2 * t4);
                float pw12 = 0.f, pw2 = 0.f;
                #pragma unroll
                for (int j = 0; j < 4; j++) {
                    float o0 = acc[(mt * 4 + j) * 4 + 2 * s + 0];
                    float o1 = acc[(mt * 4 + j) * 4 + 2 * s + 1];
                    __half2 chh = crow[j * 4];      // 8 halves apart = 4 half2
                    pw12 += o0 * __low2float(chh) + o1 * __high2float(chh);
                    pw2  += o0 * o0 + o1 * o1;
                }
                w12a[mt * 2 + s] += pw12;
                w2a[mt * 2 + s]  += pw2;
            }
        }
        __syncthreads();   // before next dt's compute consumes freshly staged buffer
    }

    // reduce partials across t4 quad (r owned by 4 lanes with same g) and across d-halves
    #pragma unroll
    for (int i = 0; i < 4; i++) {
        w12a[i] += __shfl_xor_sync(0xffffffffu, w12a[i], 1);
        w12a[i] += __shfl_xor_sync(0xffffffffu, w12a[i], 2);
        w2a[i]  += __shfl_xor_sync(0xffffffffu, w2a[i], 1);
        w2a[i]  += __shfl_xor_sync(0xffffffffu, w2a[i], 2);
    }
    // the two d-half warps (wid even/odd, same rbase) both hold partials for the same r.
    if ((wid & 1) == 0 && t4 == 0) {
        #pragma unroll
        for (int mt = 0; mt < 2; mt++)
            #pragma unroll
            for (int s = 0; s < 2; s++) {
                int r = rbase + mt * 16 + g + 8 * s;
                w12s[r] = w12a[mt * 2 + s];
                w2s[r]  = w2a[mt * 2 + s];
            }
    }
    __syncthreads();
    if ((wid & 1) == 1 && t4 == 0) {
        #pragma unroll
        for (int mt = 0; mt < 2; mt++)
            #pragma unroll
            for (int s = 0; s < 2; s++) {
                int r = rbase + mt * 16 + g + 8 * s;
                w12s[r] += w12a[mt * 2 + s];
                w2s[r]  += w2a[mt * 2 + s];
            }
    }
    __syncthreads();

    // ================= sim + LogSumExp over regions =================
    if (tid < 256) {
        int r = tid;
        float w2 = sqrtf(w2s[r]);
        float denom = fmaxf(g_w1[c * RDIM + r] * w2, 1e-8f);
        float sim = w12s[r] / denom;
        float e = __expf(LLSE * sim);
        #pragma unroll
        for (int o = 16; o; o >>= 1) e += __shfl_xor_sync(0xffffffffu, e, o);
        float* red = (float*)(smem + RED_OFF);
        if (lane == 0) red[wid] = e;
    }
    __syncthreads();
    if (tid == 0) {
        float* red = (float*)(smem + RED_OFF);
        float s = 0.f;
        #pragma unroll
        for (int i = 0; i < 8; i++) s += red[i];
        out[c * NDIM + n] = logf(s) * (1.0f / LLSE);
    }
}

// ---------------- launch ----------------
extern "C" void kernel_launch(void* const* d_in, const int* in_sizes, int n_in,
                              void* d_out, int out_size) {
    const float* contracts = (const float*)d_in[0];   // [32,256,512] fp32
    const float* laws      = (const float*)d_in[1];   // [32,256,512] fp32
    const int*   law_lens  = (const int*)d_in[2];     // [32] int32
    float* out = (float*)d_out;                        // [32,32] fp32

    cudaFuncSetAttribute(ctl_main, cudaFuncAttributeMaxDynamicSharedMemorySize, SMEM_TOTAL);

    ctl_prep_con<<<CDIM * RDIM, 128>>>(contracts);
    ctl_prep_law<<<NDIM * LDIM, 128>>>(laws);
    ctl_main<<<dim3(CDIM, NDIM), 512, SMEM_TOTAL>>>(law_lens, out);
}

// round 8
// speedup vs baseline: 1.1012x; 1.0155x over previous
#include <cuda_runtime.h>
#include <cuda_fp16.h>
#include <cstdint>

// Problem dims (fixed by reference setup_inputs)
#define CDIM 32
#define NDIM 32
#define RDIM 256
#define LDIM 256
#define DDIM 512

// fp16 scratch copies of inputs + precomputed contract row norms
__device__ __half g_con_h[CDIM * RDIM * DDIM];   // 8 MB
__device__ __half g_law_h[NDIM * LDIM * DDIM];   // 8 MB
__device__ float  g_w1[CDIM * RDIM];

// ---------------- smem layout (bytes) ----------------
#define PSTR      264                     // P row stride in halves (256 + 8 pad)
#define P_BYTES   (LDIM * PSTR * 2)       // 135168
#define ST1       72                      // staging row stride in halves (64 + 8 pad)
#define LAW1_OFF  (P_BYTES)                       // 2 x 64*72*2   = 18432
#define CON1_OFF  (LAW1_OFF + 2 * 64 * ST1 * 2)   // 2 x 256*72*2  = 73728
#define LAW2_OFF  (P_BYTES)                       // phase-2: 2 x 256*72*2 (reuse)
#define W12_OFF   (CON1_OFF + 2 * 256 * ST1 * 2)  // 227328
#define W2_OFF    (W12_OFF + 256 * 4)
#define RED_OFF   (W2_OFF + 256 * 4)
#define SMEM_TOTAL (RED_OFF + 8 * 4)              // 229408 <= 232448

#define LEAKY 0.1f
#define SMOOTH 4.0f
#define LLSE 6.0f
#define SCALE_INV_SQRTD 0.04419417382415922f   // 1/sqrt(512)

// ---------------- PTX helpers ----------------
__device__ __forceinline__ uint32_t s2u(const void* p) {
    return (uint32_t)__cvta_generic_to_shared(p);
}
__device__ __forceinline__ void cp16(uint32_t dst, const void* src) {
    asm volatile("cp.async.cg.shared.global [%0], [%1], 16;\n" :: "r"(dst), "l"(src));
}
__device__ __forceinline__ void cp16p(uint32_t dst, const void* src, int pred) {
    // predicated cp.async: only issue when pred != 0
    asm volatile("{\n\t.reg .pred p;\n\tsetp.ne.s32 p, %2, 0;\n\t"
                 "@p cp.async.cg.shared.global [%0], [%1], 16;\n\t}"
                 :: "r"(dst), "l"(src), "r"(pred));
}
__device__ __forceinline__ void cp_commit() {
    asm volatile("cp.async.commit_group;\n");
}
__device__ __forceinline__ void ldsm_x4(uint32_t& r0, uint32_t& r1, uint32_t& r2, uint32_t& r3, uint32_t a) {
    asm volatile("ldmatrix.sync.aligned.m8n8.x4.shared.b16 {%0,%1,%2,%3}, [%4];\n"
                 : "=r"(r0), "=r"(r1), "=r"(r2), "=r"(r3) : "r"(a));
}
__device__ __forceinline__ void ldsm_x4t(uint32_t& r0, uint32_t& r1, uint32_t& r2, uint32_t& r3, uint32_t a) {
    asm volatile("ldmatrix.sync.aligned.m8n8.x4.trans.shared.b16 {%0,%1,%2,%3}, [%4];\n"
                 : "=r"(r0), "=r"(r1), "=r"(r2), "=r"(r3) : "r"(a));
}
__device__ __forceinline__ void mma16816(float* c,
                                         uint32_t a0, uint32_t a1, uint32_t a2, uint32_t a3,
                                         uint32_t b0, uint32_t b1) {
    asm volatile("mma.sync.aligned.m16n8k16.row.col.f32.f16.f16.f32 "
                 "{%0,%1,%2,%3}, {%4,%5,%6,%7}, {%8,%9}, {%0,%1,%2,%3};\n"
                 : "+f"(c[0]), "+f"(c[1]), "+f"(c[2]), "+f"(c[3])
                 : "r"(a0), "r"(a1), "r"(a2), "r"(a3), "r"(b0), "r"(b1));
}

// ---------------- pre-pass kernels ----------------
__global__ void ctl_prep_con(const float* __restrict__ con) {
    int row = blockIdx.x;           // 0..8191
    int t = threadIdx.x;            // 128
    const float4* src = reinterpret_cast<const float4*>(con + (size_t)row * DDIM);
    float4 v = src[t];
    __half2* dst = reinterpret_cast<__half2*>(g_con_h + (size_t)row * DDIM);
    dst[2 * t + 0] = __floats2half2_rn(v.x, v.y);
    dst[2 * t + 1] = __floats2half2_rn(v.z, v.w);
    float ss = v.x * v.x + v.y * v.y + v.z * v.z + v.w * v.w;
    #pragma unroll
    for (int o = 16; o; o >>= 1) ss += __shfl_xor_sync(0xffffffffu, ss, o);
    __shared__ float red[4];
    if ((t & 31) == 0) red[t >> 5] = ss;
    __syncthreads();
    if (t == 0) g_w1[row] = sqrtf(red[0] + red[1] + red[2] + red[3]);
}

__global__ void ctl_prep_law(const float* __restrict__ law) {
    int row = blockIdx.x;
    int t = threadIdx.x;
    const float4* src = reinterpret_cast<const float4*>(law + (size_t)row * DDIM);
    float4 v = src[t];
    __half2* dst = reinterpret_cast<__half2*>(g_law_h + (size_t)row * DDIM);
    dst[2 * t + 0] = __floats2half2_rn(v.x, v.y);
    dst[2 * t + 1] = __floats2half2_rn(v.z, v.w);
}

// ---------------- main fused kernel: one CTA per (n, c), 512 threads ----------------
// grid = (x=n, y=c): n varies fastest in launch order so every scheduling wave
// mixes all law lengths -> balanced per-SM work sums.
__global__ __launch_bounds__(512, 1)
void ctl_main(const int* __restrict__ lens, float* __restrict__ out) {
    extern __shared__ char smem[];
    const int n = blockIdx.x;
    const int c = blockIdx.y;
    const int tid = threadIdx.x;
    const int wid = tid >> 5;        // 0..15
    const int lane = tid & 31;
    const int g = lane >> 2;         // row within 8
    const int t4 = lane & 3;

    __half* P = (__half*)smem;                                 // [256][264] fp16 attn
    __half* law1 = (__half*)(smem + LAW1_OFF);                 // [2][64][72]
    __half* con1 = (__half*)(smem + CON1_OFF);                 // [2][256][72]
    const __half* lawg = g_law_h + (size_t)n * LDIM * DDIM;
    const __half* cong = g_con_h + (size_t)c * RDIM * DDIM;
    const int len = lens[n];
    const int lcmax = (len + 63) >> 6;    // 2..4 phase-1 l-chunks actually needed
    const int ksmax = (len + 15) >> 4;    // 8..16 phase-2 k-chunks actually needed
    const int l2rows = ksmax * 16;        // phase-2 law rows actually consumed

    // ================= Phase 1: attn = softmax-ops(laws @ con^T) into P =================
    const int wl = wid >> 2;      // 0..3 -> 16 l-rows each
    const int wr = wid & 3;       // 0..3 -> 64 r-cols each

    for (int lc = 0; lc < lcmax; lc++) {
        const int l0 = lc * 64;

        auto issue = [&](int kt) {
            int buf = kt & 1;
            __half* lb = law1 + buf * (64 * ST1);
            __half* cb = con1 + buf * (256 * ST1);
            {   // laws: 64 rows x 8 chunks = 512 -> 1 per thread
                int row = tid >> 3, ch = tid & 7;
                cp16(s2u(lb + row * ST1 + ch * 8),
                     lawg + (size_t)(l0 + row) * DDIM + kt * 64 + ch * 8);
            }
            #pragma unroll
            for (int i = 0; i < 4; i++) {          // contracts: 256 rows x 8 chunks
                int id = tid + 512 * i;
                int row = id >> 3, ch = id & 7;
                cp16(s2u(cb + row * ST1 + ch * 8),
                     cong + (size_t)row * DDIM + kt * 64 + ch * 8);
            }
            cp_commit();
        };

        float acc[32];
        #pragma unroll
        for (int i = 0; i < 32; i++) acc[i] = 0.f;

        issue(0);
        for (int kt = 0; kt < 8; kt++) {
            if (kt < 7) {
                issue(kt + 1);
                asm volatile("cp.async.wait_group 1;\n");
            } else {
                asm volatile("cp.async.wait_group 0;\n");
            }
            __syncthreads();
            int buf = kt & 1;
            const __half* lb = law1 + buf * (64 * ST1);
            const __half* cb = con1 + buf * (256 * ST1);
            #pragma unroll
            for (int ks = 0; ks < 4; ks++) {
                uint32_t a0, a1, a2, a3;
                {
                    int row = wl * 16 + (lane & 15);
                    int col = ks * 16 + (lane >> 4) * 8;
                    ldsm_x4(a0, a1, a2, a3, s2u(lb + row * ST1 + col));
                }
                #pragma unroll
                for (int np = 0; np < 4; np++) {
                    uint32_t b0, b1, b2, b3;
                    int n0 = wr * 64 + np * 16;
                    int row = n0 + (lane & 7) + ((lane >> 4) << 3);
                    int col = ks * 16 + ((lane >> 3) & 1) * 8;
                    ldsm_x4(b0, b1, b2, b3, s2u(cb + row * ST1 + col));
                    mma16816(acc + (np * 2 + 0) * 4, a0, a1, a2, a3, b0, b1);
                    mma16816(acc + (np * 2 + 1) * 4, a0, a1, a2, a3, b2, b3);
                }
            }
            __syncthreads();
        }

        // scale + leaky-relu, store S chunk into P (fp16)
        {
            int lrow0 = l0 + wl * 16 + g;
            #pragma unroll
            for (int nt = 0; nt < 8; nt++) {
                int rb = wr * 64 + nt * 8 + 2 * t4;
                float v0 = acc[nt * 4 + 0] * SCALE_INV_SQRTD;
                float v1 = acc[nt * 4 + 1] * SCALE_INV_SQRTD;
                float v2 = acc[nt * 4 + 2] * SCALE_INV_SQRTD;
                float v3 = acc[nt * 4 + 3] * SCALE_INV_SQRTD;
                v0 = (v0 >= 0.f) ? v0 : LEAKY * v0;
                v1 = (v1 >= 0.f) ? v1 : LEAKY * v1;
                v2 = (v2 >= 0.f) ? v2 : LEAKY * v2;
                v3 = (v3 >= 0.f) ? v3 : LEAKY * v3;
                *(__half2*)&P[(size_t)lrow0 * PSTR + rb]       = __floats2half2_rn(v0, v1);
                *(__half2*)&P[(size_t)(lrow0 + 8) * PSTR + rb] = __floats2half2_rn(v2, v3);
            }
        }
        __syncthreads();

        // row ops (per l-row over full R): l2norm -> softmax -> *SMOOTH -> mask
        for (int rr = 0; rr < 4; rr++) {
            int l = l0 + wid * 4 + rr;
            __half2* prow = (__half2*)&P[(size_t)l * PSTR];
            float v[8];
            float ss = 0.f;
            #pragma unroll
            for (int j = 0; j < 4; j++) {
                __half2 h = prow[lane + 32 * j];
                float x = __low2float(h), y = __high2float(h);
                v[2 * j] = x; v[2 * j + 1] = y;
                ss += x * x + y * y;
            }
            #pragma unroll
            for (int o = 16; o; o >>= 1) ss += __shfl_xor_sync(0xffffffffu, ss, o);
            float inv = 1.f / (sqrtf(ss) + 1e-8f);
            float es = 0.f;
            #pragma unroll
            for (int j = 0; j < 8; j++) {
                v[j] = __expf(v[j] * inv);
                es += v[j];
            }
            #pragma unroll
            for (int o = 16; o; o >>= 1) es += __shfl_xor_sync(0xffffffffu, es, o);
            float zf = (l < len) ? (SMOOTH / es) : 0.f;
            #pragma unroll
            for (int j = 0; j < 4; j++)
                prow[lane + 32 * j] = __floats2half2_rn(v[2 * j] * zf, v[2 * j + 1] * zf);
        }
        __syncthreads();
    }

    // ================= Phase 2: wlaw = P^T @ laws, fused cosine partials =================
    // 16 warps: rbase = (wid>>1)*32 (32 r-rows), dhalf = (wid&1)*32 (32 d-cols per 64-chunk)
    // contraction over l runs only where attn can be nonzero: ks < ksmax (rest is exactly 0)
    __half* law2 = (__half*)(smem + LAW2_OFF);   // [2][256][72]
    float* w12s = (float*)(smem + W12_OFF);
    float* w2s  = (float*)(smem + W2_OFF);

    float w12a[4] = {0.f, 0.f, 0.f, 0.f};
    float w2a[4]  = {0.f, 0.f, 0.f, 0.f};
    const int rbase = (wid >> 1) * 32;
    const int dhalf = (wid & 1) * 32;

    auto stage2 = [&](int dt) {
        __half* lb = law2 + (dt & 1) * (256 * ST1);
        #pragma unroll
        for (int i = 0; i < 4; i++) {
            int id = tid + 512 * i;
            int row = id >> 3, ch = id & 7;
            cp16p(s2u(lb + row * ST1 + ch * 8),
                  lawg + (size_t)row * DDIM + dt * 64 + ch * 8,
                  row < l2rows);
        }
        cp_commit();
    };

    stage2(0);
    for (int dt = 0; dt < 8; dt++) {
        if (dt < 7) {
            stage2(dt + 1);
            asm volatile("cp.async.wait_group 1;\n");
        } else {
            asm volatile("cp.async.wait_group 0;\n");
        }
        __syncthreads();
        const __half* lb = law2 + (dt & 1) * (256 * ST1);

        float acc[32];
        #pragma unroll
        for (int i = 0; i < 32; i++) acc[i] = 0.f;

        #pragma unroll 4
        for (int ks = 0; ks < ksmax; ks++) {
            int l0k = ks * 16;
            uint32_t a[2][4];
            #pragma unroll
            for (int mt = 0; mt < 2; mt++) {
                int r0 = rbase + mt * 16;
                int row = l0k + (lane & 7) + ((lane & 16) >> 1);
                int col = r0 + (lane & 8);
                ldsm_x4t(a[mt][0], a[mt][1], a[mt][2], a[mt][3],
                         s2u(&P[(size_t)row * PSTR + col]));
            }
            #pragma unroll
            for (int np = 0; np < 2; np++) {
                uint32_t b0, b1, b2, b3;
                int d0 = dhalf + np * 16;
                int row = l0k + (lane & 7) + (lane & 8);
                int col = d0 + ((lane & 16) >> 1);
                ldsm_x4t(b0, b1, b2, b3, s2u(&lb[row * ST1 + col]));
                mma16816(acc + (0 * 4 + np * 2 + 0) * 4, a[0][0], a[0][1], a[0][2], a[0][3], b0, b1);
                mma16816(acc + (0 * 4 + np * 2 + 1) * 4, a[0][0], a[0][1], a[0][2], a[0][3], b2, b3);
                mma16816(acc + (1 * 4 + np * 2 + 0) * 4, a[1][0], a[1][1], a[1][2], a[1][3], b0, b1);
                mma16816(acc + (1 * 4 + np * 2 + 1) * 4, a[1][0], a[1][1], a[1][2], a[1][3], b2, b3);
            }
        }

        // cosine partials (con read straight from L2-resident global)
        #pragma unroll
        for (int mt = 0; mt < 2; mt++) {
            #pragma unroll
            for (int s = 0; s < 2; s++) {
                int r = rbase + mt * 16 + g + 8 * s;
                const __half2* crow = (const __half2*)(cong + (size_t)r * DDIM + dt * 64 + dhalf + 2 * t4);
                float pw12 = 0.f, pw2 = 0.f;
                #pragma unroll
                for (int j = 0; j < 4; j++) {
                    float o0 = acc[(mt * 4 + j) * 4 + 2 * s + 0];
                    float o1 = acc[(mt * 4 + j) * 4 + 2 * s + 1];
                    __half2 chh = crow[j * 4];      // 8 halves apart = 4 half2
                    pw12 += o0 * __low2float(chh) + o1 * __high2float(chh);
                    pw2  += o0 * o0 + o1 * o1;
                }
                w12a[mt * 2 + s] += pw12;
                w2a[mt * 2 + s]  += pw2;
            }
        }
        __syncthreads();   // before next dt's compute consumes freshly staged buffer
    }

    // reduce partials across t4 quad (r owned by 4 lanes with same g) and across d-halves
    #pragma unroll
    for (int i = 0; i < 4; i++) {
        w12a[i] += __shfl_xor_sync(0xffffffffu, w12a[i], 1);
        w12a[i] += __shfl_xor_sync(0xffffffffu, w12a[i], 2);
        w2a[i]  += __shfl_xor_sync(0xffffffffu, w2a[i], 1);
        w2a[i]  += __shfl_xor_sync(0xffffffffu, w2a[i], 2);
    }
    // the two d-half warps (wid even/odd, same rbase) both hold partials for the same r.
    if ((wid & 1) == 0 && t4 == 0) {
        #pragma unroll
        for (int mt = 0; mt < 2; mt++)
            #pragma unroll
            for (int s = 0; s < 2; s++) {
                int r = rbase + mt * 16 + g + 8 * s;
                w12s[r] = w12a[mt * 2 + s];
                w2s[r]  = w2a[mt * 2 + s];
            }
    }
    __syncthreads();
    if ((wid & 1) == 1 && t4 == 0) {
        #pragma unroll
        for (int mt = 0; mt < 2; mt++)
            #pragma unroll
            for (int s = 0; s < 2; s++) {
                int r = rbase + mt * 16 + g + 8 * s;
                w12s[r] += w12a[mt * 2 + s];
                w2s[r]  += w2a[mt * 2 + s];
            }
    }
    __syncthreads();

    // ================= sim + LogSumExp over regions =================
    if (tid < 256) {
        int r = tid;
        float w2 = sqrtf(w2s[r]);
        float denom = fmaxf(g_w1[c * RDIM + r] * w2, 1e-8f);
        float sim = w12s[r] / denom;
        float e = __expf(LLSE * sim);
        #pragma unroll
        for (int o = 16; o; o >>= 1) e += __shfl_xor_sync(0xffffffffu, e, o);
        float* red = (float*)(smem + RED_OFF);
        if (lane == 0) red[wid] = e;
    }
    __syncthreads();
    if (tid == 0) {
        float* red = (float*)(smem + RED_OFF);
        float s = 0.f;
        #pragma unroll
        for (int i = 0; i < 8; i++) s += red[i];
        out[c * NDIM + n] = logf(s) * (1.0f / LLSE);
    }
}

// ---------------- launch ----------------
extern "C" void kernel_launch(void* const* d_in, const int* in_sizes, int n_in,
                              void* d_out, int out_size) {
    const float* contracts = (const float*)d_in[0];   // [32,256,512] fp32
    const float* laws      = (const float*)d_in[1];   // [32,256,512] fp32
    const int*   law_lens  = (const int*)d_in[2];     // [32] int32
    float* out = (float*)d_out;                        // [32,32] fp32

    cudaFuncSetAttribute(ctl_main, cudaFuncAttributeMaxDynamicSharedMemorySize, SMEM_TOTAL);

    ctl_prep_con<<<CDIM * RDIM, 128>>>(contracts);
    ctl_prep_law<<<NDIM * LDIM, 128>>>(laws);
    // n fastest (x), c slow (y) for wave-level load balance across ragged lens
    ctl_main<<<dim3(NDIM, CDIM), 512, SMEM_TOTAL>>>(law_lens, out);
}

// round 9
// speedup vs baseline: 1.1288x; 1.0251x over previous
#include <cuda_runtime.h>
#include <cuda_fp16.h>
#include <cstdint>

// Problem dims (fixed by reference setup_inputs)
#define CDIM 32
#define NDIM 32
#define RDIM 256
#define LDIM 256
#define DDIM 512

// fp16 scratch copies of inputs + precomputed contract row norms
__device__ __half g_con_h[CDIM * RDIM * DDIM];   // 8 MB
__device__ __half g_law_h[NDIM * LDIM * DDIM];   // 8 MB
__device__ float  g_w1[CDIM * RDIM];

// ---------------- smem layout (bytes) ----------------
#define PSTR      264                     // P row stride in halves (256 + 8 pad)
#define P_BYTES   (LDIM * PSTR * 2)       // 135168
#define ST1       72                      // staging row stride in halves (64 + 8 pad)
#define LAW1_OFF  (P_BYTES)                       // 2 x 64*72*2   = 18432
#define CON1_OFF  (LAW1_OFF + 2 * 64 * ST1 * 2)   // 2 x 256*72*2  = 73728
#define LAW2_OFF  (P_BYTES)                       // phase-2: 2 x 256*72*2 (reuse)
#define W12_OFF   (CON1_OFF + 2 * 256 * ST1 * 2)  // 227328
#define W2_OFF    (W12_OFF + 256 * 4)
#define RED_OFF   (W2_OFF + 256 * 4)
#define SMEM_TOTAL (RED_OFF + 8 * 4)              // 229408 <= 232448

#define LEAKY 0.1f
#define SMOOTH 4.0f
#define LLSE 6.0f
#define SCALE_INV_SQRTD 0.04419417382415922f   // 1/sqrt(512)

// ---------------- PTX helpers ----------------
__device__ __forceinline__ uint32_t s2u(const void* p) {
    return (uint32_t)__cvta_generic_to_shared(p);
}
__device__ __forceinline__ void cp16(uint32_t dst, const void* src) {
    asm volatile("cp.async.cg.shared.global [%0], [%1], 16;\n" :: "r"(dst), "l"(src));
}
__device__ __forceinline__ void cp16p(uint32_t dst, const void* src, int pred) {
    // predicated cp.async: only issue when pred != 0
    asm volatile("{\n\t.reg .pred p;\n\tsetp.ne.s32 p, %2, 0;\n\t"
                 "@p cp.async.cg.shared.global [%0], [%1], 16;\n\t}"
                 :: "r"(dst), "l"(src), "r"(pred));
}
__device__ __forceinline__ void cp_commit() {
    asm volatile("cp.async.commit_group;\n");
}
__device__ __forceinline__ void ldsm_x4(uint32_t& r0, uint32_t& r1, uint32_t& r2, uint32_t& r3, uint32_t a) {
    asm volatile("ldmatrix.sync.aligned.m8n8.x4.shared.b16 {%0,%1,%2,%3}, [%4];\n"
                 : "=r"(r0), "=r"(r1), "=r"(r2), "=r"(r3) : "r"(a));
}
__device__ __forceinline__ void ldsm_x4t(uint32_t& r0, uint32_t& r1, uint32_t& r2, uint32_t& r3, uint32_t a) {
    asm volatile("ldmatrix.sync.aligned.m8n8.x4.trans.shared.b16 {%0,%1,%2,%3}, [%4];\n"
                 : "=r"(r0), "=r"(r1), "=r"(r2), "=r"(r3) : "r"(a));
}
__device__ __forceinline__ void mma16816(float* c,
                                         uint32_t a0, uint32_t a1, uint32_t a2, uint32_t a3,
                                         uint32_t b0, uint32_t b1) {
    asm volatile("mma.sync.aligned.m16n8k16.row.col.f32.f16.f16.f32 "
                 "{%0,%1,%2,%3}, {%4,%5,%6,%7}, {%8,%9}, {%0,%1,%2,%3};\n"
                 : "+f"(c[0]), "+f"(c[1]), "+f"(c[2]), "+f"(c[3])
                 : "r"(a0), "r"(a1), "r"(a2), "r"(a3), "r"(b0), "r"(b1));
}

// ---------------- merged pre-pass kernel ----------------
// blocks [0, 8192): contract rows (convert + norm); [8192, 16384): law rows (convert)
__global__ void ctl_prep(const float* __restrict__ con, const float* __restrict__ law) {
    int b = blockIdx.x;
    int t = threadIdx.x;            // 128
    if (b < CDIM * RDIM) {
        int row = b;
        const float4* src = reinterpret_cast<const float4*>(con + (size_t)row * DDIM);
        float4 v = src[t];
        __half2* dst = reinterpret_cast<__half2*>(g_con_h + (size_t)row * DDIM);
        dst[2 * t + 0] = __floats2half2_rn(v.x, v.y);
        dst[2 * t + 1] = __floats2half2_rn(v.z, v.w);
        float ss = v.x * v.x + v.y * v.y + v.z * v.z + v.w * v.w;
        #pragma unroll
        for (int o = 16; o; o >>= 1) ss += __shfl_xor_sync(0xffffffffu, ss, o);
        __shared__ float red[4];
        if ((t & 31) == 0) red[t >> 5] = ss;
        __syncthreads();
        if (t == 0) g_w1[row] = sqrtf(red[0] + red[1] + red[2] + red[3]);
    } else {
        int row = b - CDIM * RDIM;
        const float4* src = reinterpret_cast<const float4*>(law + (size_t)row * DDIM);
        float4 v = src[t];
        __half2* dst = reinterpret_cast<__half2*>(g_law_h + (size_t)row * DDIM);
        dst[2 * t + 0] = __floats2half2_rn(v.x, v.y);
        dst[2 * t + 1] = __floats2half2_rn(v.z, v.w);
    }
}

// ---------------- main fused kernel: one CTA per (n, c), 512 threads ----------------
// grid = (x=n, y=c): n varies fastest in launch order so every scheduling wave
// mixes all law lengths -> balanced per-SM work sums.
__global__ __launch_bounds__(512, 1)
void ctl_main(const int* __restrict__ lens, float* __restrict__ out) {
    extern __shared__ char smem[];
    const int n = blockIdx.x;
    const int c = blockIdx.y;
    const int tid = threadIdx.x;
    const int wid = tid >> 5;        // 0..15
    const int lane = tid & 31;
    const int g = lane >> 2;         // row within 8
    const int t4 = lane & 3;

    __half* P = (__half*)smem;                                 // [256][264] fp16 attn
    __half* law1 = (__half*)(smem + LAW1_OFF);                 // [2][64][72]
    __half* con1 = (__half*)(smem + CON1_OFF);                 // [2][256][72]
    const __half* lawg = g_law_h + (size_t)n * LDIM * DDIM;
    const __half* cong = g_con_h + (size_t)c * RDIM * DDIM;
    const int len = lens[n];
    const int len16 = (len + 15) & ~15;   // 16-row rounded length
    const int lcmax = (len + 63) >> 6;    // 2..4 phase-1 l-chunks actually needed
    const int ksmax = (len + 15) >> 4;    // 8..16 phase-2 k-chunks actually needed
    const int l2rows = ksmax * 16;        // phase-2 law rows actually consumed

    // ================= Phase 1: attn = softmax-ops(laws @ con^T) into P =================
    const int wl = wid >> 2;      // 0..3 -> 16 l-rows each
    const int wr = wid & 3;       // 0..3 -> 64 r-cols each

    for (int lc = 0; lc < lcmax; lc++) {
        const int l0 = lc * 64;
        // this warp's 16-row l-tile participates only if it starts below len16
        const int active = (l0 + wl * 16) < len16;

        auto issue = [&](int kt) {
            int buf = kt & 1;
            __half* lb = law1 + buf * (64 * ST1);
            __half* cb = con1 + buf * (256 * ST1);
            {   // laws: 64 rows x 8 chunks = 512 -> 1 per thread (skip rows >= len16)
                int row = tid >> 3, ch = tid & 7;
                cp16p(s2u(lb + row * ST1 + ch * 8),
                      lawg + (size_t)(l0 + row) * DDIM + kt * 64 + ch * 8,
                      (l0 + row) < len16);
            }
            #pragma unroll
            for (int i = 0; i < 4; i++) {          // contracts: 256 rows x 8 chunks
                int id = tid + 512 * i;
                int row = id >> 3, ch = id & 7;
                cp16(s2u(cb + row * ST1 + ch * 8),
                     cong + (size_t)row * DDIM + kt * 64 + ch * 8);
            }
            cp_commit();
        };

        float acc[32];
        #pragma unroll
        for (int i = 0; i < 32; i++) acc[i] = 0.f;

        issue(0);
        for (int kt = 0; kt < 8; kt++) {
            if (kt < 7) {
                issue(kt + 1);
                asm volatile("cp.async.wait_group 1;\n");
            } else {
                asm volatile("cp.async.wait_group 0;\n");
            }
            __syncthreads();
            if (active) {
                int buf = kt & 1;
                const __half* lb = law1 + buf * (64 * ST1);
                const __half* cb = con1 + buf * (256 * ST1);
                #pragma unroll
                for (int ks = 0; ks < 4; ks++) {
                    uint32_t a0, a1, a2, a3;
                    {
                        int row = wl * 16 + (lane & 15);
                        int col = ks * 16 + (lane >> 4) * 8;
                        ldsm_x4(a0, a1, a2, a3, s2u(lb + row * ST1 + col));
                    }
                    #pragma unroll
                    for (int np = 0; np < 4; np++) {
                        uint32_t b0, b1, b2, b3;
                        int n0 = wr * 64 + np * 16;
                        int row = n0 + (lane & 7) + ((lane >> 4) << 3);
                        int col = ks * 16 + ((lane >> 3) & 1) * 8;
                        ldsm_x4(b0, b1, b2, b3, s2u(cb + row * ST1 + col));
                        mma16816(acc + (np * 2 + 0) * 4, a0, a1, a2, a3, b0, b1);
                        mma16816(acc + (np * 2 + 1) * 4, a0, a1, a2, a3, b2, b3);
                    }
                }
            }
            __syncthreads();
        }

        // scale + leaky-relu, store S chunk into P (fp16)
        if (active) {
            int lrow0 = l0 + wl * 16 + g;
            #pragma unroll
            for (int nt = 0; nt < 8; nt++) {
                int rb = wr * 64 + nt * 8 + 2 * t4;
                float v0 = acc[nt * 4 + 0] * SCALE_INV_SQRTD;
                float v1 = acc[nt * 4 + 1] * SCALE_INV_SQRTD;
                float v2 = acc[nt * 4 + 2] * SCALE_INV_SQRTD;
                float v3 = acc[nt * 4 + 3] * SCALE_INV_SQRTD;
                v0 = (v0 >= 0.f) ? v0 : LEAKY * v0;
                v1 = (v1 >= 0.f) ? v1 : LEAKY * v1;
                v2 = (v2 >= 0.f) ? v2 : LEAKY * v2;
                v3 = (v3 >= 0.f) ? v3 : LEAKY * v3;
                *(__half2*)&P[(size_t)lrow0 * PSTR + rb]       = __floats2half2_rn(v0, v1);
                *(__half2*)&P[(size_t)(lrow0 + 8) * PSTR + rb] = __floats2half2_rn(v2, v3);
            }
        }
        __syncthreads();

        // row ops (per l-row over full R): l2norm -> softmax -> *SMOOTH -> mask.
        // Rows >= len are written as literal zeros (never read P there: tiles above
        // len16 were skipped and may contain garbage/NaN bit patterns).
        for (int rr = 0; rr < 4; rr++) {
            int l = l0 + wid * 4 + rr;
            __half2* prow = (__half2*)&P[(size_t)l * PSTR];
            if (l >= len) {
                #pragma unroll
                for (int j = 0; j < 4; j++)
                    prow[lane + 32 * j] = __floats2half2_rn(0.f, 0.f);
                continue;
            }
            float v[8];
            float ss = 0.f;
            #pragma unroll
            for (int j = 0; j < 4; j++) {
                __half2 h = prow[lane + 32 * j];
                float x = __low2float(h), y = __high2float(h);
                v[2 * j] = x; v[2 * j + 1] = y;
                ss += x * x + y * y;
            }
            #pragma unroll
            for (int o = 16; o; o >>= 1) ss += __shfl_xor_sync(0xffffffffu, ss, o);
            float inv = 1.f / (sqrtf(ss) + 1e-8f);
            float es = 0.f;
            #pragma unroll
            for (int j = 0; j < 8; j++) {
                v[j] = __expf(v[j] * inv);
                es += v[j];
            }
            #pragma unroll
            for (int o = 16; o; o >>= 1) es += __shfl_xor_sync(0xffffffffu, es, o);
            float zf = SMOOTH / es;
            #pragma unroll
            for (int j = 0; j < 4; j++)
                prow[lane + 32 * j] = __floats2half2_rn(v[2 * j] * zf, v[2 * j + 1] * zf);
        }
        __syncthreads();
    }

    // ================= Phase 2: wlaw = P^T @ laws, fused cosine partials =================
    // 16 warps: rbase = (wid>>1)*32 (32 r-rows), dhalf = (wid&1)*32 (32 d-cols per 64-chunk)
    // contraction over l runs only where attn can be nonzero: ks < ksmax (rest is exactly 0)
    __half* law2 = (__half*)(smem + LAW2_OFF);   // [2][256][72]
    float* w12s = (float*)(smem + W12_OFF);
    float* w2s  = (float*)(smem + W2_OFF);

    float w12a[4] = {0.f, 0.f, 0.f, 0.f};
    float w2a[4]  = {0.f, 0.f, 0.f, 0.f};
    const int rbase = (wid >> 1) * 32;
    const int dhalf = (wid & 1) * 32;

    auto stage2 = [&](int dt) {
        __half* lb = law2 + (dt & 1) * (256 * ST1);
        #pragma unroll
        for (int i = 0; i < 4; i++) {
            int id = tid + 512 * i;
            int row = id >> 3, ch = id & 7;
            cp16p(s2u(lb + row * ST1 + ch * 8),
                  lawg + (size_t)row * DDIM + dt * 64 + ch * 8,
                  row < l2rows);
        }
        cp_commit();
    };

    stage2(0);
    for (int dt = 0; dt < 8; dt++) {
        if (dt < 7) {
            stage2(dt + 1);
            asm volatile("cp.async.wait_group 1;\n");
        } else {
            asm volatile("cp.async.wait_group 0;\n");
        }
        __syncthreads();
        const __half* lb = law2 + (dt & 1) * (256 * ST1);

        float acc[32];
        #pragma unroll
        for (int i = 0; i < 32; i++) acc[i] = 0.f;

        #pragma unroll 4
        for (int ks = 0; ks < ksmax; ks++) {
            int l0k = ks * 16;
            uint32_t a[2][4];
            #pragma unroll
            for (int mt = 0; mt < 2; mt++) {
                int r0 = rbase + mt * 16;
                int row = l0k + (lane & 7) + ((lane & 16) >> 1);
                int col = r0 + (lane & 8);
                ldsm_x4t(a[mt][0], a[mt][1], a[mt][2], a[mt][3],
                         s2u(&P[(size_t)row * PSTR + col]));
            }
            #pragma unroll
            for (int np = 0; np < 2; np++) {
                uint32_t b0, b1, b2, b3;
                int d0 = dhalf + np * 16;
                int row = l0k + (lane & 7) + (lane & 8);
                int col = d0 + ((lane & 16) >> 1);
                ldsm_x4t(b0, b1, b2, b3, s2u(&lb[row * ST1 + col]));
                mma16816(acc + (0 * 4 + np * 2 + 0) * 4, a[0][0], a[0][1], a[0][2], a[0][3], b0, b1);
                mma16816(acc + (0 * 4 + np * 2 + 1) * 4, a[0][0], a[0][1], a[0][2], a[0][3], b2, b3);
                mma16816(acc + (1 * 4 + np * 2 + 0) * 4, a[1][0], a[1][1], a[1][2], a[1][3], b0, b1);
                mma16816(acc + (1 * 4 + np * 2 + 1) * 4, a[1][0], a[1][1], a[1][2], a[1][3], b2, b3);
            }
        }

        // cosine partials (con read straight from L2-resident global)
        #pragma unroll
        for (int mt = 0; mt < 2; mt++) {
            #pragma unroll
            for (int s = 0; s < 2; s++) {
                int r = rbase + mt * 16 + g + 8 * s;
                const __half2* crow = (const __half2*)(cong + (size_t)r * DDIM + dt * 64 + dhalf + 2 * t4);
                float pw12 = 0.f, pw2 = 0.f;
                #pragma unroll
                for (int j = 0; j < 4; j++) {
                    float o0 = acc[(mt * 4 + j) * 4 + 2 * s + 0];
                    float o1 = acc[(mt * 4 + j) * 4 + 2 * s + 1];
                    __half2 chh = crow[j * 4];      // 8 halves apart = 4 half2
                    pw12 += o0 * __low2float(chh) + o1 * __high2float(chh);
                    pw2  += o0 * o0 + o1 * o1;
                }
                w12a[mt * 2 + s] += pw12;
                w2a[mt * 2 + s]  += pw2;
            }
        }
        __syncthreads();   // before next dt's compute consumes freshly staged buffer
    }

    // reduce partials across t4 quad (r owned by 4 lanes with same g) and across d-halves
    #pragma unroll
    for (int i = 0; i < 4; i++) {
        w12a[i] += __shfl_xor_sync(0xffffffffu, w12a[i], 1);
        w12a[i] += __shfl_xor_sync(0xffffffffu, w12a[i], 2);
        w2a[i]  += __shfl_xor_sync(0xffffffffu, w2a[i], 1);
        w2a[i]  += __shfl_xor_sync(0xffffffffu, w2a[i], 2);
    }
    // the two d-half warps (wid even/odd, same rbase) both hold partials for the same r.
    if ((wid & 1) == 0 && t4 == 0) {
        #pragma unroll
        for (int mt = 0; mt < 2; mt++)
            #pragma unroll
            for (int s = 0; s < 2; s++) {
                int r = rbase + mt * 16 + g + 8 * s;
                w12s[r] = w12a[mt * 2 + s];
                w2s[r]  = w2a[mt * 2 + s];
            }
    }
    __syncthreads();
    if ((wid & 1) == 1 && t4 == 0) {
        #pragma unroll
        for (int mt = 0; mt < 2; mt++)
            #pragma unroll
            for (int s = 0; s < 2; s++) {
                int r = rbase + mt * 16 + g + 8 * s;
                w12s[r] += w12a[mt * 2 + s];
                w2s[r]  += w2a[mt * 2 + s];
            }
    }
    __syncthreads();

    // ================= sim + LogSumExp over regions =================
    if (tid < 256) {
        int r = tid;
        float w2 = sqrtf(w2s[r]);
        float denom = fmaxf(g_w1[c * RDIM + r] * w2, 1e-8f);
        float sim = w12s[r] / denom;
        float e = __expf(LLSE * sim);
        #pragma unroll
        for (int o = 16; o; o >>= 1) e += __shfl_xor_sync(0xffffffffu, e, o);
        float* red = (float*)(smem + RED_OFF);
        if (lane == 0) red[wid] = e;
    }
    __syncthreads();
    if (tid == 0) {
        float* red = (float*)(smem + RED_OFF);
        float s = 0.f;
        #pragma unroll
        for (int i = 0; i < 8; i++) s += red[i];
        out[c * NDIM + n] = logf(s) * (1.0f / LLSE);
    }
}

// ---------------- launch ----------------
extern "C" void kernel_launch(void* const* d_in, const int* in_sizes, int n_in,
                              void* d_out, int out_size) {
    const float* contracts = (const float*)d_in[0];   // [32,256,512] fp32
    const float* laws      = (const float*)d_in[1];   // [32,256,512] fp32
    const int*   law_lens  = (const int*)d_in[2];     // [32] int32
    float* out = (float*)d_out;                        // [32,32] fp32

    cudaFuncSetAttribute(ctl_main, cudaFuncAttributeMaxDynamicSharedMemorySize, SMEM_TOTAL);

    // merged prep (one launch) -> launch cycle (prep, main) so ncu -s 5 lands on ctl_main
    ctl_prep<<<CDIM * RDIM + NDIM * LDIM, 128>>>(contracts, laws);
    // n fastest (x), c slow (y) for wave-level load balance across ragged lens
    ctl_main<<<dim3(NDIM, CDIM), 512, SMEM_TOTAL>>>(law_lens, out);
}

// round 10
// speedup vs baseline: 1.1886x; 1.0530x over previous
#include <cuda_runtime.h>
#include <cuda_fp16.h>
#include <cstdint>

// Problem dims (fixed by reference setup_inputs)
#define CDIM 32
#define NDIM 32
#define RDIM 256
#define LDIM 256
#define DDIM 512

// fp16 scratch copies of inputs + precomputed contract row norms
__device__ __half g_con_h[CDIM * RDIM * DDIM];   // 8 MB
__device__ __half g_law_h[NDIM * LDIM * DDIM];   // 8 MB
__device__ float  g_w1[CDIM * RDIM];

// ---------------- smem layout (bytes) ----------------
#define PSTR      264                     // P row stride in halves (256 + 8 pad)
#define P_BYTES   (LDIM * PSTR * 2)       // 135168
#define ST1       72                      // staging row stride in halves (64 + 8 pad)
#define LAW1_OFF  (P_BYTES)                       // 2 x 64*72*2   = 18432
#define CON1_OFF  (LAW1_OFF + 2 * 64 * ST1 * 2)   // 2 x 256*72*2  = 73728
#define LAW2_OFF  (P_BYTES)                       // phase-2: 2 x 256*72*2 (reuse)
#define SSP_OFF   LAW1_OFF                        // epilogue ss partials [64][8] f32 (2KB)
#define ESP_OFF   (LAW1_OFF + 2048)               // epilogue es partials [64][8] f32 (2KB)
#define W12_OFF   (CON1_OFF + 2 * 256 * ST1 * 2)  // 227328
#define W2_OFF    (W12_OFF + 256 * 4)
#define RED_OFF   (W2_OFF + 256 * 4)
#define SMEM_TOTAL (RED_OFF + 8 * 4)              // 229408 <= 232448

#define LEAKY 0.1f
#define SMOOTH 4.0f
#define LLSE 6.0f
#define SCALE_INV_SQRTD 0.04419417382415922f   // 1/sqrt(512)

// ---------------- PTX helpers ----------------
__device__ __forceinline__ uint32_t s2u(const void* p) {
    return (uint32_t)__cvta_generic_to_shared(p);
}
__device__ __forceinline__ void cp16(uint32_t dst, const void* src) {
    asm volatile("cp.async.cg.shared.global [%0], [%1], 16;\n" :: "r"(dst), "l"(src));
}
__device__ __forceinline__ void cp16p(uint32_t dst, const void* src, int pred) {
    asm volatile("{\n\t.reg .pred p;\n\tsetp.ne.s32 p, %2, 0;\n\t"
                 "@p cp.async.cg.shared.global [%0], [%1], 16;\n\t}"
                 :: "r"(dst), "l"(src), "r"(pred));
}
__device__ __forceinline__ void cp_commit() {
    asm volatile("cp.async.commit_group;\n");
}
__device__ __forceinline__ void ldsm_x4(uint32_t& r0, uint32_t& r1, uint32_t& r2, uint32_t& r3, uint32_t a) {
    asm volatile("ldmatrix.sync.aligned.m8n8.x4.shared.b16 {%0,%1,%2,%3}, [%4];\n"
                 : "=r"(r0), "=r"(r1), "=r"(r2), "=r"(r3) : "r"(a));
}
__device__ __forceinline__ void ldsm_x4t(uint32_t& r0, uint32_t& r1, uint32_t& r2, uint32_t& r3, uint32_t a) {
    asm volatile("ldmatrix.sync.aligned.m8n8.x4.trans.shared.b16 {%0,%1,%2,%3}, [%4];\n"
                 : "=r"(r0), "=r"(r1), "=r"(r2), "=r"(r3) : "r"(a));
}
__device__ __forceinline__ void mma16816(float* c,
                                         uint32_t a0, uint32_t a1, uint32_t a2, uint32_t a3,
                                         uint32_t b0, uint32_t b1) {
    asm volatile("mma.sync.aligned.m16n8k16.row.col.f32.f16.f16.f32 "
                 "{%0,%1,%2,%3}, {%4,%5,%6,%7}, {%8,%9}, {%0,%1,%2,%3};\n"
                 : "+f"(c[0]), "+f"(c[1]), "+f"(c[2]), "+f"(c[3])
                 : "r"(a0), "r"(a1), "r"(a2), "r"(a3), "r"(b0), "r"(b1));
}

// ---------------- merged pre-pass kernel ----------------
__global__ void ctl_prep(const float* __restrict__ con, const float* __restrict__ law) {
    int b = blockIdx.x;
    int t = threadIdx.x;            // 128
    if (b < CDIM * RDIM) {
        int row = b;
        const float4* src = reinterpret_cast<const float4*>(con + (size_t)row * DDIM);
        float4 v = src[t];
        __half2* dst = reinterpret_cast<__half2*>(g_con_h + (size_t)row * DDIM);
        dst[2 * t + 0] = __floats2half2_rn(v.x, v.y);
        dst[2 * t + 1] = __floats2half2_rn(v.z, v.w);
        float ss = v.x * v.x + v.y * v.y + v.z * v.z + v.w * v.w;
        #pragma unroll
        for (int o = 16; o; o >>= 1) ss += __shfl_xor_sync(0xffffffffu, ss, o);
        __shared__ float red[4];
        if ((t & 31) == 0) red[t >> 5] = ss;
        __syncthreads();
        if (t == 0) g_w1[row] = sqrtf(red[0] + red[1] + red[2] + red[3]);
    } else {
        int row = b - CDIM * RDIM;
        const float4* src = reinterpret_cast<const float4*>(law + (size_t)row * DDIM);
        float4 v = src[t];
        __half2* dst = reinterpret_cast<__half2*>(g_law_h + (size_t)row * DDIM);
        dst[2 * t + 0] = __floats2half2_rn(v.x, v.y);
        dst[2 * t + 1] = __floats2half2_rn(v.z, v.w);
    }
}

// ---------------- main fused kernel: one CTA per (n, c), 512 threads ----------------
__global__ __launch_bounds__(512, 1)
void ctl_main(const int* __restrict__ lens, float* __restrict__ out) {
    extern __shared__ char smem[];
    const int n = blockIdx.x;
    const int c = blockIdx.y;
    const int tid = threadIdx.x;
    const int wid = tid >> 5;        // 0..15
    const int lane = tid & 31;
    const int g = lane >> 2;         // row within 8
    const int t4 = lane & 3;

    __half* P = (__half*)smem;                                 // [256][264] fp16 attn
    __half* law1 = (__half*)(smem + LAW1_OFF);                 // [2][64][72]
    __half* con1 = (__half*)(smem + CON1_OFF);                 // [2][256][72]
    float* ssp = (float*)(smem + SSP_OFF);                     // [64][8]
    float* esp = (float*)(smem + ESP_OFF);                     // [64][8]
    const __half* lawg = g_law_h + (size_t)n * LDIM * DDIM;
    const __half* cong = g_con_h + (size_t)c * RDIM * DDIM;
    const int len = lens[n];
    const int len16 = (len + 15) & ~15;   // 16-row rounded length
    const int lcmax = (len + 63) >> 6;    // 2..4 phase-1 l-chunks actually needed
    const int ksmax = (len + 15) >> 4;    // 8..16 phase-2 k-chunks actually needed
    const int l2rows = ksmax * 16;        // phase-2 law rows actually consumed

    // ================= Phase 1: attn = softmax-ops(laws @ con^T) into P =================
    // 32x32 warp tiles: wl in {0,1} (32 l-rows), wr in {0..7} (32 r-cols)
    const int wl = wid >> 3;
    const int wr = wid & 7;

    for (int lc = 0; lc < lcmax; lc++) {
        const int l0 = lc * 64;
        const int active = (l0 + wl * 32) < len16;

        auto issue = [&](int kt) {
            int buf = kt & 1;
            __half* lb = law1 + buf * (64 * ST1);
            __half* cb = con1 + buf * (256 * ST1);
            {   // laws: 64 rows x 8 chunks = 512 -> 1 per thread (skip rows >= len16)
                int row = tid >> 3, ch = tid & 7;
                cp16p(s2u(lb + row * ST1 + ch * 8),
                      lawg + (size_t)(l0 + row) * DDIM + kt * 64 + ch * 8,
                      (l0 + row) < len16);
            }
            #pragma unroll
            for (int i = 0; i < 4; i++) {          // contracts: 256 rows x 8 chunks
                int id = tid + 512 * i;
                int row = id >> 3, ch = id & 7;
                cp16(s2u(cb + row * ST1 + ch * 8),
                     cong + (size_t)row * DDIM + kt * 64 + ch * 8);
            }
            cp_commit();
        };

        float acc[32];
        #pragma unroll
        for (int i = 0; i < 32; i++) acc[i] = 0.f;

        issue(0);
        for (int kt = 0; kt < 8; kt++) {
            if (kt < 7) {
                issue(kt + 1);
                asm volatile("cp.async.wait_group 1;\n");
            } else {
                asm volatile("cp.async.wait_group 0;\n");
            }
            __syncthreads();
            if (active) {
                int buf = kt & 1;
                const __half* lb = law1 + buf * (64 * ST1);
                const __half* cb = con1 + buf * (256 * ST1);
                #pragma unroll
                for (int ks = 0; ks < 4; ks++) {
                    uint32_t a[2][4];
                    #pragma unroll
                    for (int mt = 0; mt < 2; mt++) {
                        int row = wl * 32 + mt * 16 + (lane & 15);
                        int col = ks * 16 + (lane >> 4) * 8;
                        ldsm_x4(a[mt][0], a[mt][1], a[mt][2], a[mt][3], s2u(lb + row * ST1 + col));
                    }
                    #pragma unroll
                    for (int np = 0; np < 2; np++) {
                        uint32_t b0, b1, b2, b3;
                        int n0 = wr * 32 + np * 16;
                        int row = n0 + (lane & 7) + ((lane >> 4) << 3);
                        int col = ks * 16 + ((lane >> 3) & 1) * 8;
                        ldsm_x4(b0, b1, b2, b3, s2u(cb + row * ST1 + col));
                        #pragma unroll
                        for (int mt = 0; mt < 2; mt++) {
                            mma16816(acc + ((mt * 2 + np) * 2 + 0) * 4, a[mt][0], a[mt][1], a[mt][2], a[mt][3], b0, b1);
                            mma16816(acc + ((mt * 2 + np) * 2 + 1) * 4, a[mt][0], a[mt][1], a[mt][2], a[mt][3], b2, b3);
                        }
                    }
                }
            }
            __syncthreads();
        }

        // ---- fused epilogue: leaky+scale in regs -> ss partials -> exp -> es -> one P write
        if (active) {
            #pragma unroll
            for (int i = 0; i < 32; i++) {
                float x = acc[i] * SCALE_INV_SQRTD;
                acc[i] = (x >= 0.f) ? x : LEAKY * x;
            }
            #pragma unroll
            for (int mt = 0; mt < 2; mt++)
                #pragma unroll
                for (int s = 0; s < 2; s++) {
                    float pw = 0.f;
                    #pragma unroll
                    for (int q = 0; q < 4; q++) {   // q = np*2 + half
                        float x0 = acc[((mt * 2) * 2 + q) * 4 + 2 * s + 0];  // careful: index below
                        (void)x0;
                    }
                    // explicit 8-term sum over (np, half)
                    #pragma unroll
                    for (int np = 0; np < 2; np++)
                        #pragma unroll
                        for (int half = 0; half < 2; half++) {
                            int base = ((mt * 2 + np) * 2 + half) * 4 + 2 * s;
                            pw += acc[base] * acc[base] + acc[base + 1] * acc[base + 1];
                        }
                    pw += __shfl_xor_sync(0xffffffffu, pw, 1);
                    pw += __shfl_xor_sync(0xffffffffu, pw, 2);
                    int row = wl * 32 + mt * 16 + g + 8 * s;
                    if (t4 == 0) ssp[row * 8 + wr] = pw;
                }
        }
        __syncthreads();
        if (active) {
            #pragma unroll
            for (int mt = 0; mt < 2; mt++)
                #pragma unroll
                for (int s = 0; s < 2; s++) {
                    int row = wl * 32 + mt * 16 + g + 8 * s;
                    float ssr = 0.f;
                    #pragma unroll
                    for (int k = 0; k < 8; k++) ssr += ssp[row * 8 + k];
                    float inv = 1.f / (sqrtf(ssr) + 1e-8f);
                    float pe = 0.f;
                    #pragma unroll
                    for (int np = 0; np < 2; np++)
                        #pragma unroll
                        for (int half = 0; half < 2; half++) {
                            int base = ((mt * 2 + np) * 2 + half) * 4 + 2 * s;
                            float e0 = __expf(acc[base] * inv);
                            float e1 = __expf(acc[base + 1] * inv);
                            acc[base] = e0; acc[base + 1] = e1;
                            pe += e0 + e1;
                        }
                    pe += __shfl_xor_sync(0xffffffffu, pe, 1);
                    pe += __shfl_xor_sync(0xffffffffu, pe, 2);
                    if (t4 == 0) esp[row * 8 + wr] = pe;
                }
        }
        __syncthreads();
        if (active) {
            #pragma unroll
            for (int mt = 0; mt < 2; mt++)
                #pragma unroll
                for (int s = 0; s < 2; s++) {
                    int row = wl * 32 + mt * 16 + g + 8 * s;
                    int l = l0 + row;
                    float es = 0.f;
                    #pragma unroll
                    for (int k = 0; k < 8; k++) es += esp[row * 8 + k];
                    float zf = (l < len) ? (SMOOTH / es) : 0.f;
                    #pragma unroll
                    for (int np = 0; np < 2; np++)
                        #pragma unroll
                        for (int half = 0; half < 2; half++) {
                            int base = ((mt * 2 + np) * 2 + half) * 4 + 2 * s;
                            int rb = wr * 32 + np * 16 + half * 8 + 2 * t4;
                            *(__half2*)&P[(size_t)l * PSTR + rb] =
                                __floats2half2_rn(acc[base] * zf, acc[base + 1] * zf);
                        }
                }
        }
        __syncthreads();
    }

    // ================= Phase 2: wlaw = P^T @ laws, fused cosine partials =================
    __half* law2 = (__half*)(smem + LAW2_OFF);   // [2][256][72]
    float* w12s = (float*)(smem + W12_OFF);
    float* w2s  = (float*)(smem + W2_OFF);

    float w12a[4] = {0.f, 0.f, 0.f, 0.f};
    float w2a[4]  = {0.f, 0.f, 0.f, 0.f};
    const int rbase = (wid >> 1) * 32;
    const int dhalf = (wid & 1) * 32;

    auto stage2 = [&](int dt) {
        __half* lb = law2 + (dt & 1) * (256 * ST1);
        #pragma unroll
        for (int i = 0; i < 4; i++) {
            int id = tid + 512 * i;
            int row = id >> 3, ch = id & 7;
            cp16p(s2u(lb + row * ST1 + ch * 8),
                  lawg + (size_t)row * DDIM + dt * 64 + ch * 8,
                  row < l2rows);
        }
        cp_commit();
    };

    stage2(0);
    for (int dt = 0; dt < 8; dt++) {
        if (dt < 7) {
            stage2(dt + 1);
            asm volatile("cp.async.wait_group 1;\n");
        } else {
            asm volatile("cp.async.wait_group 0;\n");
        }
        __syncthreads();
        const __half* lb = law2 + (dt & 1) * (256 * ST1);

        float acc[32];
        #pragma unroll
        for (int i = 0; i < 32; i++) acc[i] = 0.f;

        #pragma unroll 4
        for (int ks = 0; ks < ksmax; ks++) {
            int l0k = ks * 16;
            uint32_t a[2][4];
            #pragma unroll
            for (int mt = 0; mt < 2; mt++) {
                int r0 = rbase + mt * 16;
                int row = l0k + (lane & 7) + ((lane & 16) >> 1);
                int col = r0 + (lane & 8);
                ldsm_x4t(a[mt][0], a[mt][1], a[mt][2], a[mt][3],
                         s2u(&P[(size_t)row * PSTR + col]));
            }
            #pragma unroll
            for (int np = 0; np < 2; np++) {
                uint32_t b0, b1, b2, b3;
                int d0 = dhalf + np * 16;
                int row = l0k + (lane & 7) + (lane & 8);
                int col = d0 + ((lane & 16) >> 1);
                ldsm_x4t(b0, b1, b2, b3, s2u(&lb[row * ST1 + col]));
                mma16816(acc + (0 * 4 + np * 2 + 0) * 4, a[0][0], a[0][1], a[0][2], a[0][3], b0, b1);
                mma16816(acc + (0 * 4 + np * 2 + 1) * 4, a[0][0], a[0][1], a[0][2], a[0][3], b2, b3);
                mma16816(acc + (1 * 4 + np * 2 + 0) * 4, a[1][0], a[1][1], a[1][2], a[1][3], b0, b1);
                mma16816(acc + (1 * 4 + np * 2 + 1) * 4, a[1][0], a[1][1], a[1][2], a[1][3], b2, b3);
            }
        }

        // cosine partials (con read straight from L2-resident global)
        #pragma unroll
        for (int mt = 0; mt < 2; mt++) {
            #pragma unroll
            for (int s = 0; s < 2; s++) {
                int r = rbase + mt * 16 + g + 8 * s;
                const __half2* crow = (const __half2*)(cong + (size_t)r * DDIM + dt * 64 + dhalf + 2 * t4);
                float pw12 = 0.f, pw2 = 0.f;
                #pragma unroll
                for (int j = 0; j < 4; j++) {
                    float o0 = acc[(mt * 4 + j) * 4 + 2 * s + 0];
                    float o1 = acc[(mt * 4 + j) * 4 + 2 * s + 1];
                    __half2 chh = crow[j * 4];      // 8 halves apart = 4 half2
                    pw12 += o0 * __low2float(chh) + o1 * __high2float(chh);
                    pw2  += o0 * o0 + o1 * o1;
                }
                w12a[mt * 2 + s] += pw12;
                w2a[mt * 2 + s]  += pw2;
            }
        }
        __syncthreads();   // before next dt's compute consumes freshly staged buffer
    }

    // reduce partials across t4 quad and across d-halves
    #pragma unroll
    for (int i = 0; i < 4; i++) {
        w12a[i] += __shfl_xor_sync(0xffffffffu, w12a[i], 1);
        w12a[i] += __shfl_xor_sync(0xffffffffu, w12a[i], 2);
        w2a[i]  += __shfl_xor_sync(0xffffffffu, w2a[i], 1);
        w2a[i]  += __shfl_xor_sync(0xffffffffu, w2a[i], 2);
    }
    if ((wid & 1) == 0 && t4 == 0) {
        #pragma unroll
        for (int mt = 0; mt < 2; mt++)
            #pragma unroll
            for (int s = 0; s < 2; s++) {
                int r = rbase + mt * 16 + g + 8 * s;
                w12s[r] = w12a[mt * 2 + s];
                w2s[r]  = w2a[mt * 2 + s];
            }
    }
    __syncthreads();
    if ((wid & 1) == 1 && t4 == 0) {
        #pragma unroll
        for (int mt = 0; mt < 2; mt++)
            #pragma unroll
            for (int s = 0; s < 2; s++) {
                int r = rbase + mt * 16 + g + 8 * s;
                w12s[r] += w12a[mt * 2 + s];
                w2s[r]  += w2a[mt * 2 + s];
            }
    }
    __syncthreads();

    // ================= sim + LogSumExp over regions =================
    if (tid < 256) {
        int r = tid;
        float w2 = sqrtf(w2s[r]);
        float denom = fmaxf(g_w1[c * RDIM + r] * w2, 1e-8f);
        float sim = w12s[r] / denom;
        float e = __expf(LLSE * sim);
        #pragma unroll
        for (int o = 16; o; o >>= 1) e += __shfl_xor_sync(0xffffffffu, e, o);
        float* red = (float*)(smem + RED_OFF);
        if (lane == 0) red[wid] = e;
    }
    __syncthreads();
    if (tid == 0) {
        float* red = (float*)(smem + RED_OFF);
        float s = 0.f;
        #pragma unroll
        for (int i = 0; i < 8; i++) s += red[i];
        out[c * NDIM + n] = logf(s) * (1.0f / LLSE);
    }
}

// ---------------- launch ----------------
extern "C" void kernel_launch(void* const* d_in, const int* in_sizes, int n_in,
                              void* d_out, int out_size) {
    const float* contracts = (const float*)d_in[0];   // [32,256,512] fp32
    const float* laws      = (const float*)d_in[1];   // [32,256,512] fp32
    const int*   law_lens  = (const int*)d_in[2];     // [32] int32
    float* out = (float*)d_out;                        // [32,32] fp32

    cudaFuncSetAttribute(ctl_main, cudaFuncAttributeMaxDynamicSharedMemorySize, SMEM_TOTAL);

    ctl_prep<<<CDIM * RDIM + NDIM * LDIM, 128>>>(contracts, laws);
    ctl_main<<<dim3(NDIM, CDIM), 512, SMEM_TOTAL>>>(law_lens, out);
}

// round 14
// speedup vs baseline: 1.1968x; 1.0069x over previous
#include <cuda_runtime.h>
#include <cuda_fp16.h>
#include <cstdint>

// Problem dims (fixed by reference setup_inputs)
#define CDIM 32
#define NDIM 32
#define RDIM 256
#define LDIM 256
#define DDIM 512

// fp16 scratch copies of inputs + precomputed contract row norms
__device__ __half g_con_h[CDIM * RDIM * DDIM];   // 8 MB
__device__ __half g_law_h[NDIM * LDIM * DDIM];   // 8 MB
__device__ float  g_w1[CDIM * RDIM];

// ---------------- smem layout (bytes) ----------------
#define PSTR      264                     // P row stride in halves (256 + 8 pad)
#define P_BYTES   (LDIM * PSTR * 2)       // 135168
#define ST1       72                      // staging row stride in halves (64 + 8 pad)
#define LAW1_OFF  (P_BYTES)                       // 2 x 64*72*2   = 18432
#define CON1_OFF  (LAW1_OFF + 2 * 64 * ST1 * 2)   // 2 x 256*72*2  = 73728
#define LAW2_OFF  (P_BYTES)                       // phase-2: 2 x 256*72*2 (reuse)
#define SSP_OFF   LAW1_OFF                        // epilogue ss partials [64][8] f32 (2KB)
#define ESP_OFF   (LAW1_OFF + 2048)               // epilogue es partials [64][8] f32 (2KB)
#define W12_OFF   (CON1_OFF + 2 * 256 * ST1 * 2)  // 227328
#define W2_OFF    (W12_OFF + 256 * 4)
#define RED_OFF   (W2_OFF + 256 * 4)
#define SMEM_TOTAL (RED_OFF + 8 * 4)              // 229408 <= 232448

#define LEAKY 0.1f
#define SMOOTH 4.0f
#define LLSE 6.0f
#define SCALE_INV_SQRTD 0.04419417382415922f   // 1/sqrt(512)

// ---------------- PTX helpers ----------------
__device__ __forceinline__ uint32_t s2u(const void* p) {
    return (uint32_t)__cvta_generic_to_shared(p);
}
__device__ __forceinline__ void cp16(uint32_t dst, const void* src) {
    asm volatile("cp.async.cg.shared.global [%0], [%1], 16;\n" :: "r"(dst), "l"(src));
}
__device__ __forceinline__ void cp16p(uint32_t dst, const void* src, int pred) {
    asm volatile("{\n\t.reg .pred p;\n\tsetp.ne.s32 p, %2, 0;\n\t"
                 "@p cp.async.cg.shared.global [%0], [%1], 16;\n\t}"
                 :: "r"(dst), "l"(src), "r"(pred));
}
__device__ __forceinline__ void cp_commit() {
    asm volatile("cp.async.commit_group;\n");
}
__device__ __forceinline__ void cp_wait_all() {
    asm volatile("cp.async.wait_group 0;\n");
}
__device__ __forceinline__ void ldsm_x4(uint32_t& r0, uint32_t& r1, uint32_t& r2, uint32_t& r3, uint32_t a) {
    asm volatile("ldmatrix.sync.aligned.m8n8.x4.shared.b16 {%0,%1,%2,%3}, [%4];\n"
                 : "=r"(r0), "=r"(r1), "=r"(r2), "=r"(r3) : "r"(a));
}
__device__ __forceinline__ void ldsm_x4t(uint32_t& r0, uint32_t& r1, uint32_t& r2, uint32_t& r3, uint32_t a) {
    asm volatile("ldmatrix.sync.aligned.m8n8.x4.trans.shared.b16 {%0,%1,%2,%3}, [%4];\n"
                 : "=r"(r0), "=r"(r1), "=r"(r2), "=r"(r3) : "r"(a));
}
__device__ __forceinline__ void mma16816(float* c,
                                         uint32_t a0, uint32_t a1, uint32_t a2, uint32_t a3,
                                         uint32_t b0, uint32_t b1) {
    asm volatile("mma.sync.aligned.m16n8k16.row.col.f32.f16.f16.f32 "
                 "{%0,%1,%2,%3}, {%4,%5,%6,%7}, {%8,%9}, {%0,%1,%2,%3};\n"
                 : "+f"(c[0]), "+f"(c[1]), "+f"(c[2]), "+f"(c[3])
                 : "r"(a0), "r"(a1), "r"(a2), "r"(a3), "r"(b0), "r"(b1));
}

// ---------------- merged pre-pass kernel ----------------
__global__ void ctl_prep(const float* __restrict__ con, const float* __restrict__ law) {
    int b = blockIdx.x;
    int t = threadIdx.x;            // 128
    if (b < CDIM * RDIM) {
        int row = b;
        const float4* src = reinterpret_cast<const float4*>(con + (size_t)row * DDIM);
        float4 v = src[t];
        __half2* dst = reinterpret_cast<__half2*>(g_con_h + (size_t)row * DDIM);
        dst[2 * t + 0] = __floats2half2_rn(v.x, v.y);
        dst[2 * t + 1] = __floats2half2_rn(v.z, v.w);
        float ss = v.x * v.x + v.y * v.y + v.z * v.z + v.w * v.w;
        #pragma unroll
        for (int o = 16; o; o >>= 1) ss += __shfl_xor_sync(0xffffffffu, ss, o);
        __shared__ float red[4];
        if ((t & 31) == 0) red[t >> 5] = ss;
        __syncthreads();
        if (t == 0) g_w1[row] = sqrtf(red[0] + red[1] + red[2] + red[3]);
    } else {
        int row = b - CDIM * RDIM;
        const float4* src = reinterpret_cast<const float4*>(law + (size_t)row * DDIM);
        float4 v = src[t];
        __half2* dst = reinterpret_cast<__half2*>(g_law_h + (size_t)row * DDIM);
        dst[2 * t + 0] = __floats2half2_rn(v.x, v.y);
        dst[2 * t + 1] = __floats2half2_rn(v.z, v.w);
    }
}

// ---------------- main fused kernel: one CTA per (n, c), 512 threads ----------------
__global__ __launch_bounds__(512, 1)
void ctl_main(const int* __restrict__ lens, float* __restrict__ out) {
    extern __shared__ char smem[];
    const int n = blockIdx.x;
    const int c = blockIdx.y;
    const int tid = threadIdx.x;
    const int wid = tid >> 5;        // 0..15
    const int lane = tid & 31;
    const int g = lane >> 2;         // row within 8
    const int t4 = lane & 3;

    __half* P = (__half*)smem;                                 // [256][264] fp16 attn
    __half* law1 = (__half*)(smem + LAW1_OFF);                 // [2][64][72]
    __half* con1 = (__half*)(smem + CON1_OFF);                 // [2][256][72]
    float* ssp = (float*)(smem + SSP_OFF);                     // [64][8]
    float* esp = (float*)(smem + ESP_OFF);                     // [64][8]
    const __half* lawg = g_law_h + (size_t)n * LDIM * DDIM;
    const __half* cong = g_con_h + (size_t)c * RDIM * DDIM;
    const int len = lens[n];
    const int len16 = (len + 15) & ~15;   // 16-row rounded length
    const int lcmax = (len + 63) >> 6;    // 2..4 phase-1 l-chunks actually needed
    const int ksmax = (len + 15) >> 4;    // 8..16 phase-2 k-chunks actually needed
    const int l2rows = ksmax * 16;        // phase-2 law rows actually consumed

    // ================= Phase 1: attn = softmax-ops(laws @ con^T) into P =================
    // 32x32 warp tiles: wl in {0,1} (32 l-rows), wr in {0..7} (32 r-cols)
    const int wl = wid >> 3;
    const int wr = wid & 7;

    for (int lc = 0; lc < lcmax; lc++) {
        const int l0 = lc * 64;
        const int active = (l0 + wl * 32) < len16;

        auto issue = [&](int kt) {
            int buf = kt & 1;
            __half* lb = law1 + buf * (64 * ST1);
            __half* cb = con1 + buf * (256 * ST1);
            {   // laws: 64 rows x 8 chunks = 512 -> 1 per thread (skip rows >= len16)
                int row = tid >> 3, ch = tid & 7;
                cp16p(s2u(lb + row * ST1 + ch * 8),
                      lawg + (size_t)(l0 + row) * DDIM + kt * 64 + ch * 8,
                      (l0 + row) < len16);
            }
            #pragma unroll
            for (int i = 0; i < 4; i++) {          // contracts: 256 rows x 8 chunks
                int id = tid + 512 * i;
                int row = id >> 3, ch = id & 7;
                cp16(s2u(cb + row * ST1 + ch * 8),
                     cong + (size_t)row * DDIM + kt * 64 + ch * 8);
            }
            cp_commit();
        };

        float acc[32];
        #pragma unroll
        for (int i = 0; i < 32; i++) acc[i] = 0.f;

        issue(0);
        // single-sync pipeline: wait own cps -> barrier (visibility + WAR) -> issue next -> compute
        for (int kt = 0; kt < 8; kt++) {
            cp_wait_all();
            __syncthreads();
            if (kt < 7) issue(kt + 1);
            if (active) {
                int buf = kt & 1;
                const __half* lb = law1 + buf * (64 * ST1);
                const __half* cb = con1 + buf * (256 * ST1);
                #pragma unroll
                for (int ks = 0; ks < 4; ks++) {
                    uint32_t a[2][4];
                    #pragma unroll
                    for (int mt = 0; mt < 2; mt++) {
                        int row = wl * 32 + mt * 16 + (lane & 15);
                        int col = ks * 16 + (lane >> 4) * 8;
                        ldsm_x4(a[mt][0], a[mt][1], a[mt][2], a[mt][3], s2u(lb + row * ST1 + col));
                    }
                    #pragma unroll
                    for (int np = 0; np < 2; np++) {
                        uint32_t b0, b1, b2, b3;
                        int n0 = wr * 32 + np * 16;
                        int row = n0 + (lane & 7) + ((lane >> 4) << 3);
                        int col = ks * 16 + ((lane >> 3) & 1) * 8;
                        ldsm_x4(b0, b1, b2, b3, s2u(cb + row * ST1 + col));
                        #pragma unroll
                        for (int mt = 0; mt < 2; mt++) {
                            mma16816(acc + ((mt * 2 + np) * 2 + 0) * 4, a[mt][0], a[mt][1], a[mt][2], a[mt][3], b0, b1);
                            mma16816(acc + ((mt * 2 + np) * 2 + 1) * 4, a[mt][0], a[mt][1], a[mt][2], a[mt][3], b2, b3);
                        }
                    }
                }
            }
        }
        __syncthreads();   // all compute done before epilogue reuses staging area (ssp/esp)

        // ---- fused epilogue: leaky+scale in regs -> ss partials -> exp -> es -> one P write
        if (active) {
            #pragma unroll
            for (int i = 0; i < 32; i++) {
                float x = acc[i] * SCALE_INV_SQRTD;
                acc[i] = (x >= 0.f) ? x : LEAKY * x;
            }
            #pragma unroll
            for (int mt = 0; mt < 2; mt++)
                #pragma unroll
                for (int s = 0; s < 2; s++) {
                    float pw = 0.f;
                    #pragma unroll
                    for (int np = 0; np < 2; np++)
                        #pragma unroll
                        for (int half = 0; half < 2; half++) {
                            int base = ((mt * 2 + np) * 2 + half) * 4 + 2 * s;
                            pw += acc[base] * acc[base] + acc[base + 1] * acc[base + 1];
                        }
                    pw += __shfl_xor_sync(0xffffffffu, pw, 1);
                    pw += __shfl_xor_sync(0xffffffffu, pw, 2);
                    int row = wl * 32 + mt * 16 + g + 8 * s;
                    if (t4 == 0) ssp[row * 8 + wr] = pw;
                }
        }
        __syncthreads();
        if (active) {
            #pragma unroll
            for (int mt = 0; mt < 2; mt++)
                #pragma unroll
                for (int s = 0; s < 2; s++) {
                    int row = wl * 32 + mt * 16 + g + 8 * s;
                    float ssr = 0.f;
                    #pragma unroll
                    for (int k = 0; k < 8; k++) ssr += ssp[row * 8 + k];
                    float inv = 1.f / (sqrtf(ssr) + 1e-8f);
                    float pe = 0.f;
                    #pragma unroll
                    for (int np = 0; np < 2; np++)
                        #pragma unroll
                        for (int half = 0; half < 2; half++) {
                            int base = ((mt * 2 + np) * 2 + half) * 4 + 2 * s;
                            float e0 = __expf(acc[base] * inv);
                            float e1 = __expf(acc[base + 1] * inv);
                            acc[base] = e0; acc[base + 1] = e1;
                            pe += e0 + e1;
                        }
                    pe += __shfl_xor_sync(0xffffffffu, pe, 1);
                    pe += __shfl_xor_sync(0xffffffffu, pe, 2);
                    if (t4 == 0) esp[row * 8 + wr] = pe;
                }
        }
        __syncthreads();
        if (active) {
            #pragma unroll
            for (int mt = 0; mt < 2; mt++)
                #pragma unroll
                for (int s = 0; s < 2; s++) {
                    int row = wl * 32 + mt * 16 + g + 8 * s;
                    int l = l0 + row;
                    float es = 0.f;
                    #pragma unroll
                    for (int k = 0; k < 8; k++) es += esp[row * 8 + k];
                    float zf = (l < len) ? (SMOOTH / es) : 0.f;
                    #pragma unroll
                    for (int np = 0; np < 2; np++)
                        #pragma unroll
                        for (int half = 0; half < 2; half++) {
                            int base = ((mt * 2 + np) * 2 + half) * 4 + 2 * s;
                            int rb = wr * 32 + np * 16 + half * 8 + 2 * t4;
                            *(__half2*)&P[(size_t)l * PSTR + rb] =
                                __floats2half2_rn(acc[base] * zf, acc[base + 1] * zf);
                        }
                }
        }
        __syncthreads();
    }

    // ================= Phase 2: wlaw = P^T @ laws, fused cosine partials =================
    __half* law2 = (__half*)(smem + LAW2_OFF);   // [2][256][72]
    float* w12s = (float*)(smem + W12_OFF);
    float* w2s  = (float*)(smem + W2_OFF);

    float w12a[4] = {0.f, 0.f, 0.f, 0.f};
    float w2a[4]  = {0.f, 0.f, 0.f, 0.f};
    const int rbase = (wid >> 1) * 32;
    const int dhalf = (wid & 1) * 32;

    auto stage2 = [&](int dt) {
        __half* lb = law2 + (dt & 1) * (256 * ST1);
        #pragma unroll
        for (int i = 0; i < 4; i++) {
            int id = tid + 512 * i;
            int row = id >> 3, ch = id & 7;
            cp16p(s2u(lb + row * ST1 + ch * 8),
                  lawg + (size_t)row * DDIM + dt * 64 + ch * 8,
                  row < l2rows);
        }
        cp_commit();
    };

    stage2(0);
    // single-sync pipeline (same proof as phase 1)
    for (int dt = 0; dt < 8; dt++) {
        cp_wait_all();
        __syncthreads();
        if (dt < 7) stage2(dt + 1);
        const __half* lb = law2 + (dt & 1) * (256 * ST1);

        float acc[32];
        #pragma unroll
        for (int i = 0; i < 32; i++) acc[i] = 0.f;

        #pragma unroll 4
        for (int ks = 0; ks < ksmax; ks++) {
            int l0k = ks * 16;
            uint32_t a[2][4];
            #pragma unroll
            for (int mt = 0; mt < 2; mt++) {
                int r0 = rbase + mt * 16;
                int row = l0k + (lane & 7) + ((lane & 16) >> 1);
                int col = r0 + (lane & 8);
                ldsm_x4t(a[mt][0], a[mt][1], a[mt][2], a[mt][3],
                         s2u(&P[(size_t)row * PSTR + col]));
            }
            #pragma unroll
            for (int np = 0; np < 2; np++) {
                uint32_t b0, b1, b2, b3;
                int d0 = dhalf + np * 16;
                int row = l0k + (lane & 7) + (lane & 8);
                int col = d0 + ((lane & 16) >> 1);
                ldsm_x4t(b0, b1, b2, b3, s2u(&lb[row * ST1 + col]));
                mma16816(acc + (0 * 4 + np * 2 + 0) * 4, a[0][0], a[0][1], a[0][2], a[0][3], b0, b1);
                mma16816(acc + (0 * 4 + np * 2 + 1) * 4, a[0][0], a[0][1], a[0][2], a[0][3], b2, b3);
                mma16816(acc + (1 * 4 + np * 2 + 0) * 4, a[1][0], a[1][1], a[1][2], a[1][3], b0, b1);
                mma16816(acc + (1 * 4 + np * 2 + 1) * 4, a[1][0], a[1][1], a[1][2], a[1][3], b2, b3);
            }
        }

        // cosine partials (con read straight from L2-resident global)
        #pragma unroll
        for (int mt = 0; mt < 2; mt++) {
            #pragma unroll
            for (int s = 0; s < 2; s++) {
                int r = rbase + mt * 16 + g + 8 * s;
                const __half2* crow = (const __half2*)(cong + (size_t)r * DDIM + dt * 64 + dhalf + 2 * t4);
                float pw12 = 0.f, pw2 = 0.f;
                #pragma unroll
                for (int j = 0; j < 4; j++) {
                    float o0 = acc[(mt * 4 + j) * 4 + 2 * s + 0];
                    float o1 = acc[(mt * 4 + j) * 4 + 2 * s + 1];
                    __half2 chh = crow[j * 4];      // 8 halves apart = 4 half2
                    pw12 += o0 * __low2float(chh) + o1 * __high2float(chh);
                    pw2  += o0 * o0 + o1 * o1;
                }
                w12a[mt * 2 + s] += pw12;
                w2a[mt * 2 + s]  += pw2;
            }
        }
    }
    __syncthreads();   // phase-2 compute fully done before partial-combine reuses smem

    // reduce partials across t4 quad and across d-halves
    #pragma unroll
    for (int i = 0; i < 4; i++) {
        w12a[i] += __shfl_xor_sync(0xffffffffu, w12a[i], 1);
        w12a[i] += __shfl_xor_sync(0xffffffffu, w12a[i], 2);
        w2a[i]  += __shfl_xor_sync(0xffffffffu, w2a[i], 1);
        w2a[i]  += __shfl_xor_sync(0xffffffffu, w2a[i], 2);
    }
    if ((wid & 1) == 0 && t4 == 0) {
        #pragma unroll
        for (int mt = 0; mt < 2; mt++)
            #pragma unroll
            for (int s = 0; s < 2; s++) {
                int r = rbase + mt * 16 + g + 8 * s;
                w12s[r] = w12a[mt * 2 + s];
                w2s[r]  = w2a[mt * 2 + s];
            }
    }
    __syncthreads();
    if ((wid & 1) == 1 && t4 == 0) {
        #pragma unroll
        for (int mt = 0; mt < 2; mt++)
            #pragma unroll
            for (int s = 0; s < 2; s++) {
                int r = rbase + mt * 16 + g + 8 * s;
                w12s[r] += w12a[mt * 2 + s];
                w2s[r]  += w2a[mt * 2 + s];
            }
    }
    __syncthreads();

    // ================= sim + LogSumExp over regions =================
    if (tid < 256) {
        int r = tid;
        float w2 = sqrtf(w2s[r]);
        float denom = fmaxf(g_w1[c * RDIM + r] * w2, 1e-8f);
        float sim = w12s[r] / denom;
        float e = __expf(LLSE * sim);
        #pragma unroll
        for (int o = 16; o; o >>= 1) e += __shfl_xor_sync(0xffffffffu, e, o);
        float* red = (float*)(smem + RED_OFF);
        if (lane == 0) red[wid] = e;
    }
    __syncthreads();
    if (tid == 0) {
        float* red = (float*)(smem + RED_OFF);
        float s = 0.f;
        #pragma unroll
        for (int i = 0; i < 8; i++) s += red[i];
        out[c * NDIM + n] = logf(s) * (1.0f / LLSE);
    }
}

// ---------------- launch ----------------
extern "C" void kernel_launch(void* const* d_in, const int* in_sizes, int n_in,
                              void* d_out, int out_size) {
    const float* contracts = (const float*)d_in[0];   // [32,256,512] fp32
    const float* laws      = (const float*)d_in[1];   // [32,256,512] fp32
    const int*   law_lens  = (const int*)d_in[2];     // [32] int32
    float* out = (float*)d_out;                        // [32,32] fp32

    cudaFuncSetAttribute(ctl_main, cudaFuncAttributeMaxDynamicSharedMemorySize, SMEM_TOTAL);

    ctl_prep<<<CDIM * RDIM + NDIM * LDIM, 128>>>(contracts, laws);
    ctl_main<<<dim3(NDIM, CDIM), 512, SMEM_TOTAL>>>(law_lens, out);
}

// round 15
// speedup vs baseline: 1.2259x; 1.0243x over previous
#include <cuda_runtime.h>
#include <cuda_fp16.h>
#include <cstdint>

// Problem dims (fixed by reference setup_inputs)
#define CDIM 32
#define NDIM 32
#define RDIM 256
#define LDIM 256
#define DDIM 512

// fp16 scratch copies of inputs + precomputed contract row norms
__device__ __half g_con_h[CDIM * RDIM * DDIM];   // 8 MB
__device__ __half g_law_h[NDIM * LDIM * DDIM];   // 8 MB
__device__ float  g_w1[CDIM * RDIM];

// ---------------- smem layout (bytes) ----------------
#define PSTR      264                     // P row stride in halves (256 + 8 pad)
#define P_BYTES   (LDIM * PSTR * 2)       // 135168
#define STW       40                      // phase-1 staging row stride in halves (32 + 8)
#define ST1       72                      // phase-2 staging row stride in halves (64 + 8)
#define LAW1_OFF  (P_BYTES)                       // 2 x 128*40*2 = 20480
#define CON1_OFF  (LAW1_OFF + 2 * 128 * STW * 2)  // 155648; 2 x 256*40*2 = 40960 -> 196608
#define LAW2_OFF  (P_BYTES)                       // phase-2: 2 x 256*72*2 = 73728 -> 208896
#define SSP_OFF   LAW1_OFF                        // epilogue ss partials [128][8] f32 (4KB)
#define ESP_OFF   (LAW1_OFF + 4096)               // epilogue es partials [128][8] f32 (4KB)
#define W12_OFF   (LAW2_OFF + 2 * 256 * ST1 * 2)  // 208896
#define W2_OFF    (W12_OFF + 256 * 4)
#define RED_OFF   (W2_OFF + 256 * 4)
#define SMEM_TOTAL (RED_OFF + 8 * 4)              // 210976 <= 232448

#define LEAKY 0.1f
#define SMOOTH 4.0f
#define LLSE 6.0f
#define SCALE_INV_SQRTD 0.04419417382415922f   // 1/sqrt(512)

// ---------------- PTX helpers ----------------
__device__ __forceinline__ uint32_t s2u(const void* p) {
    return (uint32_t)__cvta_generic_to_shared(p);
}
__device__ __forceinline__ void cp16(uint32_t dst, const void* src) {
    asm volatile("cp.async.cg.shared.global [%0], [%1], 16;\n" :: "r"(dst), "l"(src));
}
__device__ __forceinline__ void cp16p(uint32_t dst, const void* src, int pred) {
    asm volatile("{\n\t.reg .pred p;\n\tsetp.ne.s32 p, %2, 0;\n\t"
                 "@p cp.async.cg.shared.global [%0], [%1], 16;\n\t}"
                 :: "r"(dst), "l"(src), "r"(pred));
}
__device__ __forceinline__ void cp_commit() {
    asm volatile("cp.async.commit_group;\n");
}
__device__ __forceinline__ void cp_wait_all() {
    asm volatile("cp.async.wait_group 0;\n");
}
__device__ __forceinline__ void ldsm_x4(uint32_t& r0, uint32_t& r1, uint32_t& r2, uint32_t& r3, uint32_t a) {
    asm volatile("ldmatrix.sync.aligned.m8n8.x4.shared.b16 {%0,%1,%2,%3}, [%4];\n"
                 : "=r"(r0), "=r"(r1), "=r"(r2), "=r"(r3) : "r"(a));
}
__device__ __forceinline__ void ldsm_x4t(uint32_t& r0, uint32_t& r1, uint32_t& r2, uint32_t& r3, uint32_t a) {
    asm volatile("ldmatrix.sync.aligned.m8n8.x4.trans.shared.b16 {%0,%1,%2,%3}, [%4];\n"
                 : "=r"(r0), "=r"(r1), "=r"(r2), "=r"(r3) : "r"(a));
}
__device__ __forceinline__ void mma16816(float* c,
                                         uint32_t a0, uint32_t a1, uint32_t a2, uint32_t a3,
                                         uint32_t b0, uint32_t b1) {
    asm volatile("mma.sync.aligned.m16n8k16.row.col.f32.f16.f16.f32 "
                 "{%0,%1,%2,%3}, {%4,%5,%6,%7}, {%8,%9}, {%0,%1,%2,%3};\n"
                 : "+f"(c[0]), "+f"(c[1]), "+f"(c[2]), "+f"(c[3])
                 : "r"(a0), "r"(a1), "r"(a2), "r"(a3), "r"(b0), "r"(b1));
}

// ---------------- merged pre-pass kernel ----------------
__global__ void ctl_prep(const float* __restrict__ con, const float* __restrict__ law) {
    int b = blockIdx.x;
    int t = threadIdx.x;            // 128
    if (b < CDIM * RDIM) {
        int row = b;
        const float4* src = reinterpret_cast<const float4*>(con + (size_t)row * DDIM);
        float4 v = src[t];
        __half2* dst = reinterpret_cast<__half2*>(g_con_h + (size_t)row * DDIM);
        dst[2 * t + 0] = __floats2half2_rn(v.x, v.y);
        dst[2 * t + 1] = __floats2half2_rn(v.z, v.w);
        float ss = v.x * v.x + v.y * v.y + v.z * v.z + v.w * v.w;
        #pragma unroll
        for (int o = 16; o; o >>= 1) ss += __shfl_xor_sync(0xffffffffu, ss, o);
        __shared__ float red[4];
        if ((t & 31) == 0) red[t >> 5] = ss;
        __syncthreads();
        if (t == 0) g_w1[row] = sqrtf(red[0] + red[1] + red[2] + red[3]);
    } else {
        int row = b - CDIM * RDIM;
        const float4* src = reinterpret_cast<const float4*>(law + (size_t)row * DDIM);
        float4 v = src[t];
        __half2* dst = reinterpret_cast<__half2*>(g_law_h + (size_t)row * DDIM);
        dst[2 * t + 0] = __floats2half2_rn(v.x, v.y);
        dst[2 * t + 1] = __floats2half2_rn(v.z, v.w);
    }
}

// ---------------- main fused kernel: one CTA per (n, c), 512 threads ----------------
__global__ __launch_bounds__(512, 1)
void ctl_main(const int* __restrict__ lens, float* __restrict__ out) {
    extern __shared__ char smem[];
    const int n = blockIdx.x;
    const int c = blockIdx.y;
    const int tid = threadIdx.x;
    const int wid = tid >> 5;        // 0..15
    const int lane = tid & 31;
    const int g = lane >> 2;         // row within 8
    const int t4 = lane & 3;

    __half* P = (__half*)smem;                                 // [256][264] fp16 attn
    __half* law1 = (__half*)(smem + LAW1_OFF);                 // [2][128][40]
    __half* con1 = (__half*)(smem + CON1_OFF);                 // [2][256][40]
    float* ssp = (float*)(smem + SSP_OFF);                     // [128][8]
    float* esp = (float*)(smem + ESP_OFF);                     // [128][8]
    const __half* lawg = g_law_h + (size_t)n * LDIM * DDIM;
    const __half* cong = g_con_h + (size_t)c * RDIM * DDIM;
    const int len = lens[n];
    const int len16 = (len + 15) & ~15;   // 16-row rounded length
    const int pmax = (len + 127) >> 7;    // 1..2 phase-1 passes of 128 l-rows
    const int ksmax = (len + 15) >> 4;    // 8..16 phase-2 k-chunks actually needed
    const int l2rows = ksmax * 16;        // phase-2 law rows actually consumed

    // ================= Phase 1: attn = softmax-ops(laws @ con^T) into P =================
    // 64x32 warp tiles: wl in {0,1} (64 l-rows), wr in {0..7} (32 r-cols); pass = 128l x 256r
    const int wl = wid >> 3;
    const int wr = wid & 7;

    for (int pc = 0; pc < pmax; pc++) {
        const int l0 = pc * 128;
        const int wbase = l0 + wl * 64;
        const int active_any = wbase < len16;

        auto issue = [&](int kt) {   // stage 32 k-cols of laws (128 rows) + con (256 rows)
            int buf = kt & 1;
            __half* lb = law1 + buf * (128 * STW);
            __half* cb = con1 + buf * (256 * STW);
            {   // laws: 128 rows x 4 chunks of 16B = 512 -> 1 per thread
                int row = tid >> 2, ch = tid & 3;
                cp16p(s2u(lb + row * STW + ch * 8),
                      lawg + (size_t)(l0 + row) * DDIM + kt * 32 + ch * 8,
                      (l0 + row) < len16);
            }
            #pragma unroll
            for (int i = 0; i < 2; i++) {   // con: 256 rows x 4 chunks = 1024 -> 2 per thread
                int id = tid + 512 * i;
                int row = id >> 2, ch = id & 3;
                cp16(s2u(cb + row * STW + ch * 8),
                     cong + (size_t)row * DDIM + kt * 32 + ch * 8);
            }
            cp_commit();
        };

        float acc[64];
        #pragma unroll
        for (int i = 0; i < 64; i++) acc[i] = 0.f;

        issue(0);
        // single-sync pipeline: wait own cps -> barrier -> issue next -> compute
        for (int kt = 0; kt < 16; kt++) {
            cp_wait_all();
            __syncthreads();
            if (kt < 15) issue(kt + 1);
            if (active_any) {
                int buf = kt & 1;
                const __half* lb = law1 + buf * (128 * STW);
                const __half* cb = con1 + buf * (256 * STW);
                #pragma unroll
                for (int ks = 0; ks < 2; ks++) {
                    uint32_t b[2][4];
                    #pragma unroll
                    for (int np = 0; np < 2; np++) {
                        int row = wr * 32 + np * 16 + (lane & 7) + ((lane >> 4) << 3);
                        int col = ks * 16 + ((lane >> 3) & 1) * 8;
                        ldsm_x4(b[np][0], b[np][1], b[np][2], b[np][3], s2u(cb + row * STW + col));
                    }
                    #pragma unroll
                    for (int mt = 0; mt < 4; mt++) {
                        if ((wbase + mt * 16) < len16) {
                            uint32_t a0, a1, a2, a3;
                            int row = wl * 64 + mt * 16 + (lane & 15);
                            int col = ks * 16 + (lane >> 4) * 8;
                            ldsm_x4(a0, a1, a2, a3, s2u(lb + row * STW + col));
                            #pragma unroll
                            for (int np = 0; np < 2; np++) {
                                mma16816(acc + ((mt * 2 + np) * 2 + 0) * 4, a0, a1, a2, a3, b[np][0], b[np][1]);
                                mma16816(acc + ((mt * 2 + np) * 2 + 1) * 4, a0, a1, a2, a3, b[np][2], b[np][3]);
                            }
                        }
                    }
                }
            }
        }
        __syncthreads();   // all compute done before epilogue reuses staging area (ssp/esp)

        // ---- fused epilogue: leaky+scale in regs -> ss partials -> exp -> es -> one P write
        // inactive mt sub-tiles hold acc=0 -> harmless (zf=0 masks their P rows to zero)
        if (active_any) {
            #pragma unroll
            for (int i = 0; i < 64; i++) {
                float x = acc[i] * SCALE_INV_SQRTD;
                acc[i] = (x >= 0.f) ? x : LEAKY * x;
            }
            #pragma unroll
            for (int mt = 0; mt < 4; mt++)
                #pragma unroll
                for (int s = 0; s < 2; s++) {
                    float pw = 0.f;
                    #pragma unroll
                    for (int np = 0; np < 2; np++)
                        #pragma unroll
                        for (int half = 0; half < 2; half++) {
                            int base = ((mt * 2 + np) * 2 + half) * 4 + 2 * s;
                            pw += acc[base] * acc[base] + acc[base + 1] * acc[base + 1];
                        }
                    pw += __shfl_xor_sync(0xffffffffu, pw, 1);
                    pw += __shfl_xor_sync(0xffffffffu, pw, 2);
                    int row = wl * 64 + mt * 16 + g + 8 * s;
                    if (t4 == 0) ssp[row * 8 + wr] = pw;
                }
        }
        __syncthreads();
        if (active_any) {
            #pragma unroll
            for (int mt = 0; mt < 4; mt++)
                #pragma unroll
                for (int s = 0; s < 2; s++) {
                    int row = wl * 64 + mt * 16 + g + 8 * s;
                    float ssr = 0.f;
                    #pragma unroll
                    for (int k = 0; k < 8; k++) ssr += ssp[row * 8 + k];
                    float inv = 1.f / (sqrtf(ssr) + 1e-8f);
                    float pe = 0.f;
                    #pragma unroll
                    for (int np = 0; np < 2; np++)
                        #pragma unroll
                        for (int half = 0; half < 2; half++) {
                            int base = ((mt * 2 + np) * 2 + half) * 4 + 2 * s;
                            float e0 = __expf(acc[base] * inv);
                            float e1 = __expf(acc[base + 1] * inv);
                            acc[base] = e0; acc[base + 1] = e1;
                            pe += e0 + e1;
                        }
                    pe += __shfl_xor_sync(0xffffffffu, pe, 1);
                    pe += __shfl_xor_sync(0xffffffffu, pe, 2);
                    if (t4 == 0) esp[row * 8 + wr] = pe;
                }
        }
        __syncthreads();
        if (active_any) {
            #pragma unroll
            for (int mt = 0; mt < 4; mt++)
                #pragma unroll
                for (int s = 0; s < 2; s++) {
                    int row = wl * 64 + mt * 16 + g + 8 * s;
                    int l = l0 + row;
                    float es = 0.f;
                    #pragma unroll
                    for (int k = 0; k < 8; k++) es += esp[row * 8 + k];
                    float zf = (l < len) ? (SMOOTH / es) : 0.f;
                    #pragma unroll
                    for (int np = 0; np < 2; np++)
                        #pragma unroll
                        for (int half = 0; half < 2; half++) {
                            int base = ((mt * 2 + np) * 2 + half) * 4 + 2 * s;
                            int rb = wr * 32 + np * 16 + half * 8 + 2 * t4;
                            *(__half2*)&P[(size_t)l * PSTR + rb] =
                                __floats2half2_rn(acc[base] * zf, acc[base + 1] * zf);
                        }
                }
        }
        __syncthreads();
    }

    // ================= Phase 2: wlaw = P^T @ laws, fused cosine partials =================
    __half* law2 = (__half*)(smem + LAW2_OFF);   // [2][256][72]
    float* w12s = (float*)(smem + W12_OFF);
    float* w2s  = (float*)(smem + W2_OFF);

    float w12a[4] = {0.f, 0.f, 0.f, 0.f};
    float w2a[4]  = {0.f, 0.f, 0.f, 0.f};
    const int rbase = (wid >> 1) * 32;
    const int dhalf = (wid & 1) * 32;

    auto stage2 = [&](int dt) {
        __half* lb = law2 + (dt & 1) * (256 * ST1);
        #pragma unroll
        for (int i = 0; i < 4; i++) {
            int id = tid + 512 * i;
            int row = id >> 3, ch = id & 7;
            cp16p(s2u(lb + row * ST1 + ch * 8),
                  lawg + (size_t)row * DDIM + dt * 64 + ch * 8,
                  row < l2rows);
        }
        cp_commit();
    };

    stage2(0);
    // single-sync pipeline (same proof as phase 1)
    for (int dt = 0; dt < 8; dt++) {
        cp_wait_all();
        __syncthreads();
        if (dt < 7) stage2(dt + 1);
        const __half* lb = law2 + (dt & 1) * (256 * ST1);

        float acc[32];
        #pragma unroll
        for (int i = 0; i < 32; i++) acc[i] = 0.f;

        #pragma unroll 4
        for (int ks = 0; ks < ksmax; ks++) {
            int l0k = ks * 16;
            uint32_t a[2][4];
            #pragma unroll
            for (int mt = 0; mt < 2; mt++) {
                int r0 = rbase + mt * 16;
                int row = l0k + (lane & 7) + ((lane & 16) >> 1);
                int col = r0 + (lane & 8);
                ldsm_x4t(a[mt][0], a[mt][1], a[mt][2], a[mt][3],
                         s2u(&P[(size_t)row * PSTR + col]));
            }
            #pragma unroll
            for (int np = 0; np < 2; np++) {
                uint32_t b0, b1, b2, b3;
                int d0 = dhalf + np * 16;
                int row = l0k + (lane & 7) + (lane & 8);
                int col = d0 + ((lane & 16) >> 1);
                ldsm_x4t(b0, b1, b2, b3, s2u(&lb[row * ST1 + col]));
                mma16816(acc + (0 * 4 + np * 2 + 0) * 4, a[0][0], a[0][1], a[0][2], a[0][3], b0, b1);
                mma16816(acc + (0 * 4 + np * 2 + 1) * 4, a[0][0], a[0][1], a[0][2], a[0][3], b2, b3);
                mma16816(acc + (1 * 4 + np * 2 + 0) * 4, a[1][0], a[1][1], a[1][2], a[1][3], b0, b1);
                mma16816(acc + (1 * 4 + np * 2 + 1) * 4, a[1][0], a[1][1], a[1][2], a[1][3], b2, b3);
            }
        }

        // cosine partials (con read straight from L2-resident global)
        #pragma unroll
        for (int mt = 0; mt < 2; mt++) {
            #pragma unroll
            for (int s = 0; s < 2; s++) {
                int r = rbase + mt * 16 + g + 8 * s;
                const __half2* crow = (const __half2*)(cong + (size_t)r * DDIM + dt * 64 + dhalf + 2 * t4);
                float pw12 = 0.f, pw2 = 0.f;
                #pragma unroll
                for (int j = 0; j < 4; j++) {
                    float o0 = acc[(mt * 4 + j) * 4 + 2 * s + 0];
                    float o1 = acc[(mt * 4 + j) * 4 + 2 * s + 1];
                    __half2 chh = crow[j * 4];      // 8 halves apart = 4 half2
                    pw12 += o0 * __low2float(chh) + o1 * __high2float(chh);
                    pw2  += o0 * o0 + o1 * o1;
                }
                w12a[mt * 2 + s] += pw12;
                w2a[mt * 2 + s]  += pw2;
            }
        }
    }
    __syncthreads();   // phase-2 compute fully done before partial-combine reuses smem

    // reduce partials across t4 quad and across d-halves
    #pragma unroll
    for (int i = 0; i < 4; i++) {
        w12a[i] += __shfl_xor_sync(0xffffffffu, w12a[i], 1);
        w12a[i] += __shfl_xor_sync(0xffffffffu, w12a[i], 2);
        w2a[i]  += __shfl_xor_sync(0xffffffffu, w2a[i], 1);
        w2a[i]  += __shfl_xor_sync(0xffffffffu, w2a[i], 2);
    }
    if ((wid & 1) == 0 && t4 == 0) {
        #pragma unroll
        for (int mt = 0; mt < 2; mt++)
            #pragma unroll
            for (int s = 0; s < 2; s++) {
                int r = rbase + mt * 16 + g + 8 * s;
                w12s[r] = w12a[mt * 2 + s];
                w2s[r]  = w2a[mt * 2 + s];
            }
    }
    __syncthreads();
    if ((wid & 1) == 1 && t4 == 0) {
        #pragma unroll
        for (int mt = 0; mt < 2; mt++)
            #pragma unroll
            for (int s = 0; s < 2; s++) {
                int r = rbase + mt * 16 + g + 8 * s;
                w12s[r] += w12a[mt * 2 + s];
                w2s[r]  += w2a[mt * 2 + s];
            }
    }
    __syncthreads();

    // ================= sim + LogSumExp over regions =================
    if (tid < 256) {
        int r = tid;
        float w2 = sqrtf(w2s[r]);
        float denom = fmaxf(g_w1[c * RDIM + r] * w2, 1e-8f);
        float sim = w12s[r] / denom;
        float e = __expf(LLSE * sim);
        #pragma unroll
        for (int o = 16; o; o >>= 1) e += __shfl_xor_sync(0xffffffffu, e, o);
        float* red = (float*)(smem + RED_OFF);
        if (lane == 0) red[wid] = e;
    }
    __syncthreads();
    if (tid == 0) {
        float* red = (float*)(smem + RED_OFF);
        float s = 0.f;
        #pragma unroll
        for (int i = 0; i < 8; i++) s += red[i];
        out[c * NDIM + n] = logf(s) * (1.0f / LLSE);
    }
}

// ---------------- launch ----------------
extern "C" void kernel_launch(void* const* d_in, const int* in_sizes, int n_in,
                              void* d_out, int out_size) {
    const float* contracts = (const float*)d_in[0];   // [32,256,512] fp32
    const float* laws      = (const float*)d_in[1];   // [32,256,512] fp32
    const int*   law_lens  = (const int*)d_in[2];     // [32] int32
    float* out = (float*)d_out;                        // [32,32] fp32

    cudaFuncSetAttribute(ctl_main, cudaFuncAttributeMaxDynamicSharedMemorySize, SMEM_TOTAL);

    ctl_prep<<<CDIM * RDIM + NDIM * LDIM, 128>>>(contracts, laws);
    ctl_main<<<dim3(NDIM, CDIM), 512, SMEM_TOTAL>>>(law_lens, out);
}